// round 11
// baseline (speedup 1.0000x reference)
#include <cuda_runtime.h>
#include <cuda_fp16.h>
#include <cstdint>
#include <cstddef>

#define T_LEN 16384
#define NTOT  131072
#define NBLK  16

#define DELTA 0.015625f     // 2^-6
#define C1    0.984375f     // 1 - 2^-6

// ---------------- activations, time-major [n][ch], (hi, merged) fp16 planes ----------------
__device__ __align__(16) __half g_Xh[2][(size_t)NTOT * 128];
__device__ __align__(16) __half g_Xm[2][(size_t)NTOT * 128];
__device__ __align__(16) __half g_ZhP[(size_t)NBLK * NTOT * 128];
__device__ __align__(16) __half g_ZmP[(size_t)NBLK * NTOT * 128];
__device__ __align__(16) __half g_ShP[(size_t)NTOT * 256];
__device__ __align__(16) __half g_SmP[(size_t)NTOT * 256];
__device__ __align__(16) __half g_HhP[(size_t)NTOT * 256];
__device__ __align__(16) __half g_HmP[(size_t)NTOT * 256];

// weight blocks: [plane2][row128][k16] fp16 = 4096 elems per block (planes: Wh, Wm)
__device__ __align__(16) __half g_WFG[(size_t)NBLK * 2 * 16 * 4096];
__device__ __align__(16) __half g_WRS[(size_t)NBLK * 8 * 4096];
__device__ __align__(16) __half g_WSK[(size_t)2 * 128 * 4096];
__device__ __align__(16) __half g_W1b[(size_t)2 * 16 * 4096];
__device__ __align__(16) __half g_W2b[(size_t)2 * 16 * 4096];
__device__ float g_Bsk[256];

// ---------------- helpers ----------------
__device__ __forceinline__ uint32_t smem_u32(const void* p) {
    uint32_t a;
    asm("{ .reg .u64 t; cvta.to.shared.u64 t, %1; cvt.u32.u64 %0, t; }" : "=r"(a) : "l"(p));
    return a;
}
// activation split: h = fp16(v), m = fp16(2^-6*h + (v - h))
__device__ __forceinline__ void msplit(float v, __half& h, __half& m) {
    h = __float2half(v);
    float hf = __half2float(h);
    m = __float2half(DELTA * hf + (v - hf));
}
// weight split: h = fp16(v), m = fp16(h + 64*(v - h))
__device__ __forceinline__ void wsplit(float v, __half& h, __half& m) {
    h = __float2half(v);
    float hf = __half2float(h);
    m = __float2half(hf + 64.0f * (v - hf));
}
__device__ __forceinline__ float safe_tanh(float x) {
    float ax = fabsf(x);
    float e = __expf(-2.0f * ax);
    return copysignf((1.0f - e) / (1.0f + e), x);
}
__device__ __forceinline__ float sigmoidf_(float x) { return 1.0f / (1.0f + __expf(-x)); }

// ---------------- packing ----------------
__global__ void pack_fg(const float* __restrict__ Wf, const float* __restrict__ Wg) {
    int idx = blockIdx.x * blockDim.x + threadIdx.x;
    int kin = idx & 15, row = (idx >> 4) & 127, c = (idx >> 11) & 15;
    int nt = (idx >> 15) & 1, l = idx >> 16;
    int m = nt * 128 + row, ch = m >> 1, isg = m & 1;
    int tap = (c < 8) ? 1 : 0;
    int cin = (c & 7) * 16 + kin;
    float v = 0.f;
    if (ch < 120 && cin < 120) {
        const float* s = isg ? Wg : Wf;
        v = s[(((size_t)l * 120 + ch) * 120 + cin) * 2 + tap];
    }
    __half h, mo; wsplit(v, h, mo);
    __half* blk = g_WFG + ((size_t)((l * 2 + nt) * 16 + c)) * 4096;
    blk[row * 16 + kin] = h;
    blk[2048 + row * 16 + kin] = mo;
}

__global__ void pack_rs(const float* __restrict__ Wres) {
    int idx = blockIdx.x * blockDim.x + threadIdx.x;
    int kin = idx & 15, row = (idx >> 4) & 127, c = (idx >> 11) & 7, l = idx >> 14;
    int cin = c * 16 + kin;
    float v = (row < 120 && cin < 120) ? Wres[((size_t)l * 120 + row) * 120 + cin] : 0.f;
    __half h, mo; wsplit(v, h, mo);
    __half* blk = g_WRS + ((size_t)(l * 8 + c)) * 4096;
    blk[row * 16 + kin] = h;
    blk[2048 + row * 16 + kin] = mo;
}

__global__ void pack_sk(const float* __restrict__ Wskip, const float* __restrict__ bskip) {
    int idx = blockIdx.x * blockDim.x + threadIdx.x;
    int kin = idx & 15, row = (idx >> 4) & 127, c = (idx >> 11) & 127, nt = idx >> 18;
    int q = nt * 128 + row, lay = c >> 3, cin = (c & 7) * 16 + kin;
    float v = (q < 240 && cin < 120) ? Wskip[((size_t)lay * 240 + q) * 120 + cin] : 0.f;
    __half h, mo; wsplit(v, h, mo);
    __half* blk = g_WSK + ((size_t)(nt * 128 + c)) * 4096;
    blk[row * 16 + kin] = h;
    blk[2048 + row * 16 + kin] = mo;
    if (idx < 256) {
        float s = 0.f;
        if (idx < 240) for (int j = 0; j < NBLK; j++) s += bskip[j * 240 + idx];
        g_Bsk[idx] = s;
    }
}

__global__ void pack_h(const float* __restrict__ W1, const float* __restrict__ W2) {
    int idx = blockIdx.x * blockDim.x + threadIdx.x;
    int kin = idx & 15, row = (idx >> 4) & 127, c = (idx >> 11) & 15, nt = idx >> 15;
    int q = nt * 128 + row, k = c * 16 + kin;
    float v1 = (k < 240) ? W1[(size_t)q * 240 + k] : 0.f;
    float v2 = W2[(size_t)q * 256 + k];
    __half h, mo;
    __half* b1 = g_W1b + ((size_t)(nt * 16 + c)) * 4096;
    __half* b2 = g_W2b + ((size_t)(nt * 16 + c)) * 4096;
    wsplit(v1, h, mo); b1[row * 16 + kin] = h; b1[2048 + row * 16 + kin] = mo;
    wsplit(v2, h, mo); b2[row * 16 + kin] = h; b2[2048 + row * 16 + kin] = mo;
}

__global__ void init_kernel(const float* __restrict__ wave,
                            const float* __restrict__ W_in,
                            const float* __restrict__ b_in) {
    int idx = blockIdx.x * blockDim.x + threadIdx.x;
    int n = idx >> 7, c = idx & 127;
    float x = (c < 120) ? (W_in[c] * wave[n] + b_in[c]) : 0.f;
    __half h, m; msplit(x, h, m);
    g_Xh[0][idx] = h; g_Xm[0][idx] = m;
}

// ---------------- asm macros ----------------
#define CPA16(dst, src, sz) \
    asm volatile("cp.async.cg.shared.global [%0], [%1], 16, %2;" \
                 :: "r"(dst), "l"(src), "r"(sz) : "memory")
#define CP_COMMIT() asm volatile("cp.async.commit_group;" ::: "memory")
#define CP_WAIT1()  asm volatile("cp.async.wait_group 1;" ::: "memory")
#define CP_WAIT2()  asm volatile("cp.async.wait_group 2;" ::: "memory")

#define LDM4(rr, addr) \
    asm volatile("ldmatrix.sync.aligned.m8n8.x4.shared.b16 {%0,%1,%2,%3}, [%4];" \
                 : "=r"((rr)[0]), "=r"((rr)[1]), "=r"((rr)[2]), "=r"((rr)[3]) : "r"(addr))

#define MMA(cr, a, b0v, b1v) \
    asm volatile("mma.sync.aligned.m16n8k16.row.col.f32.f16.f16.f32 " \
                 "{%0,%1,%2,%3}, {%4,%5,%6,%7}, {%8,%9}, {%0,%1,%2,%3};" \
                 : "+f"((cr)[0]), "+f"((cr)[1]), "+f"((cr)[2]), "+f"((cr)[3]) \
                 : "r"((a)[0]), "r"((a)[1]), "r"((a)[2]), "r"((a)[3]), "r"(b0v), "r"(b1v))

// ---------------- fused FG + RES kernel: CTA 128(time) x 256(col), 512 thr ----------------
// Stage slot (36864B): Ah@0(6144) Am@6144 Wh@12288(12288) Wm@24576. 3 stages.
// z tile planes: zh@110592 (34816B), zm@110592+34816. pitch 272.
#define SLOT  36864u
#define ZOFF  110592u
#define ZPIT  272u
#define ZPL   34816u
#define FS_BYTES (110592 + 2 * 34816)

__global__ void __launch_bounds__(512, 1) fgres_kernel(int layer, int dil,
        const float* __restrict__ bf, const float* __restrict__ bg,
        const float* __restrict__ bres) {
    extern __shared__ __align__(16) char sm[];
    const int tid = threadIdx.x, lane = tid & 31, wid = tid >> 5;
    const int wn = wid >> 3, wc = wid & 7;      // 2 time-groups(64) x 8 col-groups(32)
    const int n0 = blockIdx.x * 128;
    const uint32_t smb = smem_u32(sm);

    const __half* Xrh = g_Xh[layer & 1];
    const __half* Xrm = g_Xm[layer & 1];
    __half* Xwh = g_Xh[(layer + 1) & 1];
    __half* Xwm = g_Xm[(layer + 1) & 1];
    const __half* Wb  = g_WFG + (size_t)layer * 2 * 16 * 4096;
    const __half* WRb = g_WRS + (size_t)layer * 8 * 4096;

    uint32_t offA[4], offB[2], offRB;
    {
        int rA = wn * 64 + (lane & 15);
        int cA = (lane >> 4) * 16;
#pragma unroll
        for (int i = 0; i < 4; i++) offA[i] = (uint32_t)((rA + i * 16) * 48 + cA);
        int rB = wc * 32 + (lane >> 4) * 8 + (lane & 7);
        int cB = ((lane >> 3) & 1) * 16;
        offB[0] = (uint32_t)(rB * 48 + cB);
        offB[1] = (uint32_t)((rB + 16) * 48 + cB);
        int rR = wc * 16 + (lane >> 4) * 8 + (lane & 7);
        offRB = (uint32_t)(rR * 48 + cB);
    }

    float acc1[4][4][4], acc2[4][4][4];
#pragma unroll
    for (int i = 0; i < 4; i++)
#pragma unroll
        for (int j = 0; j < 4; j++)
#pragma unroll
            for (int k = 0; k < 4; k++) { acc1[i][j][k] = 0.f; acc2[i][j][k] = 0.f; }

#define FSTAGE(cc, s) do {                                                        \
        {   /* A: 2 planes x 128 rows x 32B = 8KB, exactly 1 op/thread */         \
            int p = tid >> 8, r = (tid >> 1) & 127, hh = tid & 1;                 \
            int na = n0 + r, nn = na, sz = 16, ch0;                               \
            if ((cc) < 8) ch0 = (cc) * 16;                                        \
            else {                                                                \
                ch0 = ((cc) - 8) * 16;                                            \
                int t = na & (T_LEN - 1);                                         \
                if (t >= dil) nn = na - dil; else sz = 0;                         \
            }                                                                     \
            uint32_t d = smb + (s) * SLOT + p * 6144u + r * 48u + hh * 16u;       \
            const __half* gp = (p ? Xrm : Xrh) + (size_t)nn * 128 + ch0 + hh * 8; \
            CPA16(d, gp, sz);                                                     \
        }                                                                         \
        _Pragma("unroll")                                                         \
        for (int ii = 0; ii < 2; ii++) {   /* W: 2 planes x 256 rows x 32B = 16KB */ \
            int u = tid + ii * 512, p = (u >> 9) & 1, r = (u >> 1) & 255, hh = u & 1; \
            uint32_t d = smb + (s) * SLOT + 12288u + p * 12288u + r * 48u + hh * 16u; \
            const __half* sp = Wb + ((size_t)((r >> 7) * 16 + (cc))) * 4096       \
                               + p * 2048 + (r & 127) * 16 + hh * 8;              \
            CPA16(d, sp, 16);                                                     \
        }                                                                         \
    } while (0)

    FSTAGE(0, 0); CP_COMMIT();
    FSTAGE(1, 1); CP_COMMIT();

#pragma unroll 1
    for (int c = 0; c < 16; c++) {
        CP_WAIT1();
        __syncthreads();
        if (c + 2 < 16) FSTAGE(c + 2, (c + 2) % 3);
        CP_COMMIT();

        const uint32_t base = smb + (uint32_t)(c % 3) * SLOT;
        uint32_t A1[4][4], A2[4][4], Bf[2][4];
#pragma unroll
        for (int i = 0; i < 4; i++) {
            LDM4(A1[i], base + offA[i]);
            LDM4(A2[i], base + 6144u + offA[i]);
        }
        LDM4(Bf[0], base + 12288u + offB[0]);
        LDM4(Bf[1], base + 12288u + offB[1]);
#pragma unroll
        for (int i = 0; i < 4; i++)
#pragma unroll
            for (int j = 0; j < 4; j++)
                MMA(acc1[i][j], A1[i], Bf[j >> 1][(j & 1) * 2], Bf[j >> 1][(j & 1) * 2 + 1]);
        LDM4(Bf[0], base + 24576u + offB[0]);
        LDM4(Bf[1], base + 24576u + offB[1]);
#pragma unroll
        for (int i = 0; i < 4; i++)
#pragma unroll
            for (int j = 0; j < 4; j++)
                MMA(acc2[i][j], A2[i], Bf[j >> 1][(j & 1) * 2], Bf[j >> 1][(j & 1) * 2 + 1]);
    }
#undef FSTAGE

    // RES W prefetch (overlaps z epilogue). Stage: Wh@0 (128x48), Wm@6144.
#define RSTAGE(rc, s) do {                                                        \
        int p = tid >> 8, r = (tid >> 1) & 127, hh = tid & 1;                     \
        uint32_t d = smb + (s) * SLOT + p * 6144u + r * 48u + hh * 16u;           \
        const __half* sp = WRb + (size_t)(rc) * 4096 + p * 2048 + r * 16 + hh * 8; \
        CPA16(d, sp, 16);                                                         \
    } while (0)

    __syncthreads();   // all FG reads of stage slots done before RES W overwrites
    RSTAGE(0, 0); CP_COMMIT();
    RSTAGE(1, 1); CP_COMMIT();

    // ---- epilogue 1: z = tanh(f)*sigmoid(g); split-store to SMEM z planes + gmem ----
#pragma unroll
    for (int j = 0; j < 4; j++) {
        int c0 = wc * 32 + j * 8 + (lane & 3) * 2;
        int ch = c0 >> 1;
        float bfv = 0.f, bgv = 0.f;
        if (ch < 120) { bfv = bf[layer * 120 + ch]; bgv = bg[layer * 120 + ch]; }
#pragma unroll
        for (int i = 0; i < 4; i++)
#pragma unroll
            for (int h = 0; h < 2; h++) {
                int row = wn * 64 + i * 16 + h * 8 + (lane >> 2);
                float f = C1 * acc1[i][j][h * 2]     + acc2[i][j][h * 2]     + bfv;
                float g = C1 * acc1[i][j][h * 2 + 1] + acc2[i][j][h * 2 + 1] + bgv;
                float z = safe_tanh(f) * sigmoidf_(g);
                __half zh, zm; msplit(z, zh, zm);
                *reinterpret_cast<__half*>(sm + ZOFF + row * ZPIT + ch * 2) = zh;
                *reinterpret_cast<__half*>(sm + ZOFF + ZPL + row * ZPIT + ch * 2) = zm;
                size_t off = (size_t)layer * NTOT * 128 + (size_t)(n0 + row) * 128 + ch;
                g_ZhP[off] = zh; g_ZmP[off] = zm;
            }
    }

    // ---- RES GEMM: res[128t x 128ch] = z @ Wres^T (z from SMEM planes) ----
    float rc1[4][2][4], rc2[4][2][4];
#pragma unroll
    for (int i = 0; i < 4; i++)
#pragma unroll
        for (int j = 0; j < 2; j++)
#pragma unroll
            for (int k = 0; k < 4; k++) { rc1[i][j][k] = 0.f; rc2[i][j][k] = 0.f; }

#pragma unroll 1
    for (int rc = 0; rc < 8; rc++) {
        CP_WAIT1();
        __syncthreads();
        if (rc + 2 < 8) RSTAGE(rc + 2, (rc + 2) % 3);
        CP_COMMIT();

        const uint32_t base = smb + (uint32_t)(rc % 3) * SLOT;
        uint32_t Z1[4][4], Z2[4][4], RB[4];
        uint32_t zk = (uint32_t)(rc * 32) + (lane >> 4) * 16;
#pragma unroll
        for (int i = 0; i < 4; i++) {
            uint32_t zr = smb + ZOFF + (wn * 64 + i * 16 + (lane & 15)) * ZPIT + zk;
            LDM4(Z1[i], zr);
            LDM4(Z2[i], zr + ZPL);
        }
        LDM4(RB, base + offRB);
#pragma unroll
        for (int i = 0; i < 4; i++)
#pragma unroll
            for (int j = 0; j < 2; j++)
                MMA(rc1[i][j], Z1[i], RB[j * 2], RB[j * 2 + 1]);
        LDM4(RB, base + 6144u + offRB);
#pragma unroll
        for (int i = 0; i < 4; i++)
#pragma unroll
            for (int j = 0; j < 2; j++)
                MMA(rc2[i][j], Z2[i], RB[j * 2], RB[j * 2 + 1]);
    }
#undef RSTAGE

    // ---- epilogue 2: X_next = X + res + bres, split-stored ----
#pragma unroll
    for (int j = 0; j < 2; j++) {
        int col = wc * 16 + j * 8 + (lane & 3) * 2;
        if (col < 120) {
            float bv0 = bres[layer * 120 + col];
            float bv1 = bres[layer * 120 + col + 1];
#pragma unroll
            for (int i = 0; i < 4; i++)
#pragma unroll
                for (int h = 0; h < 2; h++) {
                    int row = n0 + wn * 64 + i * 16 + h * 8 + (lane >> 2);
                    size_t off = (size_t)row * 128 + col;
                    __half2 xh = *reinterpret_cast<const __half2*>(Xrh + off);
                    __half2 xm = *reinterpret_cast<const __half2*>(Xrm + off);
                    float x0 = C1 * __half2float(xh.x) + __half2float(xm.x)
                             + C1 * rc1[i][j][h * 2] + rc2[i][j][h * 2] + bv0;
                    float x1 = C1 * __half2float(xh.y) + __half2float(xm.y)
                             + C1 * rc1[i][j][h * 2 + 1] + rc2[i][j][h * 2 + 1] + bv1;
                    __half h0, m0, h1, m1;
                    msplit(x0, h0, m0); msplit(x1, h1, m1);
                    __half2 hp; hp.x = h0; hp.y = h1;
                    __half2 mp; mp.x = m0; mp.y = m1;
                    *reinterpret_cast<__half2*>(Xwh + off) = hp;
                    *reinterpret_cast<__half2*>(Xwm + off) = mp;
                }
        }
    }
}

// ---------------- generic GEMM (SKIP / H1 / H2): CTA 128 x 256, 512 thr, 4 stages ----------------
template<int MODE, int NCH>
__global__ void __launch_bounds__(512, 1) mma_kernel(const float* __restrict__ bA,
                                                     float* __restrict__ dout) {
    extern __shared__ __align__(16) char sm[];
    const int tid = threadIdx.x, lane = tid & 31, wid = tid >> 5;
    const int wn = wid >> 3, wc = wid & 7;
    const int n0 = blockIdx.x * 128;
    const uint32_t smb = smem_u32(sm);

    const __half *Wfam, *APh, *APm;
    int NB, CHW;
    if (MODE == 2)      { Wfam = g_WSK; NB = 128; APh = g_ZhP; APm = g_ZmP; CHW = 128; }
    else if (MODE == 3) { Wfam = g_W1b; NB = 16;  APh = g_ShP; APm = g_SmP; CHW = 256; }
    else                { Wfam = g_W2b; NB = 16;  APh = g_HhP; APm = g_HmP; CHW = 256; }

    uint32_t offA[4], offB[2];
    {
        int rA = wn * 64 + (lane & 15);
        int cA = (lane >> 4) * 16;
#pragma unroll
        for (int i = 0; i < 4; i++) offA[i] = (uint32_t)((rA + i * 16) * 48 + cA);
        int rB = wc * 32 + (lane >> 4) * 8 + (lane & 7);
        int cB = ((lane >> 3) & 1) * 16;
        offB[0] = (uint32_t)(rB * 48 + cB);
        offB[1] = (uint32_t)((rB + 16) * 48 + cB);
    }

    float acc1[4][4][4], acc2[4][4][4];
#pragma unroll
    for (int i = 0; i < 4; i++)
#pragma unroll
        for (int j = 0; j < 4; j++)
#pragma unroll
            for (int k = 0; k < 4; k++) { acc1[i][j][k] = 0.f; acc2[i][j][k] = 0.f; }

#define STAGE(cc, s) do {                                                         \
        {   /* A: 2 planes, 1 op/thread */                                        \
            int p = tid >> 8, r = (tid >> 1) & 127, hh = tid & 1;                 \
            int ch0; const __half* ap = p ? APm : APh;                            \
            if (MODE == 2) {                                                      \
                ch0 = ((cc) & 7) * 16;                                            \
                ap += (size_t)((cc) >> 3) * NTOT * 128;                           \
            } else ch0 = (cc) * 16;                                               \
            uint32_t d = smb + (s) * SLOT + p * 6144u + r * 48u + hh * 16u;       \
            CPA16(d, ap + (size_t)(n0 + r) * CHW + ch0 + hh * 8, 16);             \
        }                                                                         \
        _Pragma("unroll")                                                         \
        for (int ii = 0; ii < 2; ii++) {                                          \
            int u = tid + ii * 512, p = (u >> 9) & 1, r = (u >> 1) & 255, hh = u & 1; \
            uint32_t d = smb + (s) * SLOT + 12288u + p * 12288u + r * 48u + hh * 16u; \
            const __half* sp = Wfam + ((size_t)((r >> 7) * NB + (cc))) * 4096     \
                               + p * 2048 + (r & 127) * 16 + hh * 8;              \
            CPA16(d, sp, 16);                                                     \
        }                                                                         \
    } while (0)

    STAGE(0, 0); CP_COMMIT();
    STAGE(1, 1); CP_COMMIT();
    STAGE(2, 2); CP_COMMIT();

#pragma unroll 1
    for (int c = 0; c < NCH; c++) {
        CP_WAIT2();
        __syncthreads();
        if (c + 3 < NCH) STAGE(c + 3, (c + 3) & 3);
        CP_COMMIT();

        const uint32_t base = smb + (uint32_t)(c & 3) * SLOT;
        uint32_t A1[4][4], A2[4][4], Bf[2][4];
#pragma unroll
        for (int i = 0; i < 4; i++) {
            LDM4(A1[i], base + offA[i]);
            LDM4(A2[i], base + 6144u + offA[i]);
        }
        LDM4(Bf[0], base + 12288u + offB[0]);
        LDM4(Bf[1], base + 12288u + offB[1]);
#pragma unroll
        for (int i = 0; i < 4; i++)
#pragma unroll
            for (int j = 0; j < 4; j++)
                MMA(acc1[i][j], A1[i], Bf[j >> 1][(j & 1) * 2], Bf[j >> 1][(j & 1) * 2 + 1]);
        LDM4(Bf[0], base + 24576u + offB[0]);
        LDM4(Bf[1], base + 24576u + offB[1]);
#pragma unroll
        for (int i = 0; i < 4; i++)
#pragma unroll
            for (int j = 0; j < 4; j++)
                MMA(acc2[i][j], A2[i], Bf[j >> 1][(j & 1) * 2], Bf[j >> 1][(j & 1) * 2 + 1]);
    }
#undef STAGE

#pragma unroll
    for (int j = 0; j < 4; j++) {
        const int col = wc * 32 + j * 8 + (lane & 3) * 2;
        float bv0, bv1;
        if (MODE == 2) { bv0 = g_Bsk[col]; bv1 = g_Bsk[col + 1]; }
        else           { bv0 = bA[col]; bv1 = bA[col + 1]; }
#pragma unroll
        for (int i = 0; i < 4; i++)
#pragma unroll
            for (int h = 0; h < 2; h++) {
                int na = n0 + wn * 64 + i * 16 + h * 8 + (lane >> 2);
                float v0 = C1 * acc1[i][j][h * 2]     + acc2[i][j][h * 2]     + bv0;
                float v1 = C1 * acc1[i][j][h * 2 + 1] + acc2[i][j][h * 2 + 1] + bv1;
                if (MODE == 2 || MODE == 3) {
                    float r0 = fmaxf(v0, 0.f), r1 = fmaxf(v1, 0.f);
                    __half h0, m0, h1, m1;
                    msplit(r0, h0, m0); msplit(r1, h1, m1);
                    __half2 hp; hp.x = h0; hp.y = h1;
                    __half2 mp; mp.x = m0; mp.y = m1;
                    __half* Oh = (MODE == 2) ? g_ShP : g_HhP;
                    __half* Om = (MODE == 2) ? g_SmP : g_HmP;
                    *reinterpret_cast<__half2*>(Oh + (size_t)na * 256 + col) = hp;
                    *reinterpret_cast<__half2*>(Om + (size_t)na * 256 + col) = mp;
                } else {
                    int b = na >> 14, t = na & (T_LEN - 1);
                    dout[((size_t)b * 256 + col) * T_LEN + t]     = v0;
                    dout[((size_t)b * 256 + col + 1) * T_LEN + t] = v1;
                }
            }
    }
}

// ---------------- launch ----------------
extern "C" void kernel_launch(void* const* d_in, const int* in_sizes, int n_in,
                              void* d_out, int out_size) {
    const float* wave  = (const float*)d_in[0];
    const float* W_in  = (const float*)d_in[1];
    const float* b_in  = (const float*)d_in[2];
    const float* Wf    = (const float*)d_in[3];
    const float* bf    = (const float*)d_in[4];
    const float* Wg    = (const float*)d_in[5];
    const float* bg    = (const float*)d_in[6];
    const float* Wres  = (const float*)d_in[7];
    const float* bres  = (const float*)d_in[8];
    const float* Wskip = (const float*)d_in[9];
    const float* bskip = (const float*)d_in[10];
    const float* W1    = (const float*)d_in[11];
    const float* b1    = (const float*)d_in[12];
    const float* W2    = (const float*)d_in[13];
    const float* b2    = (const float*)d_in[14];
    float* out = (float*)d_out;

    const int GS = 4 * SLOT;   // 147456 for generic kernels
    cudaFuncSetAttribute(fgres_kernel, cudaFuncAttributeMaxDynamicSharedMemorySize, FS_BYTES);
    cudaFuncSetAttribute(mma_kernel<2, 128>, cudaFuncAttributeMaxDynamicSharedMemorySize, GS);
    cudaFuncSetAttribute(mma_kernel<3, 16>,  cudaFuncAttributeMaxDynamicSharedMemorySize, GS);
    cudaFuncSetAttribute(mma_kernel<4, 16>,  cudaFuncAttributeMaxDynamicSharedMemorySize, GS);

    pack_fg<<<16 * 2 * 16 * 2048 / 256, 256>>>(Wf, Wg);
    pack_rs<<<16 * 8 * 2048 / 256, 256>>>(Wres);
    pack_sk<<<2 * 128 * 2048 / 256, 256>>>(Wskip, bskip);
    pack_h <<<2 * 16 * 2048 / 256, 256>>>(W1, W2);
    init_kernel<<<(size_t)NTOT * 128 / 256, 256>>>(wave, W_in, b_in);

    static const int dil[NBLK] = {1, 2, 4, 8, 16, 32, 64, 128,
                                  1, 2, 4, 8, 16, 32, 64, 128};

    for (int i = 0; i < NBLK; i++)
        fgres_kernel<<<NTOT / 128, 512, FS_BYTES>>>(i, dil[i], bf, bg, bres);

    mma_kernel<2, 128><<<NTOT / 128, 512, GS>>>(nullptr, nullptr);  // batched skip
    mma_kernel<3, 16><<<NTOT / 128, 512, GS>>>(b1, nullptr);        // head1
    mma_kernel<4, 16><<<NTOT / 128, 512, GS>>>(b2, out);            // head2
}

// round 12
// speedup vs baseline: 1.7999x; 1.7999x over previous
#include <cuda_runtime.h>
#include <cuda_fp16.h>
#include <cstdint>
#include <cstddef>

#define T_LEN 16384
#define NTOT  131072
#define NBLK  16

#define DELTA 0.015625f     // 2^-6
#define C1    0.984375f     // 1 - 2^-6

// ---------------- activations, time-major [n][ch], (hi, merged) fp16 planes ----------------
__device__ __align__(16) __half g_Xh[2][(size_t)NTOT * 128];
__device__ __align__(16) __half g_Xm[2][(size_t)NTOT * 128];
__device__ __align__(16) __half g_ZhP[(size_t)NBLK * NTOT * 128];
__device__ __align__(16) __half g_ZmP[(size_t)NBLK * NTOT * 128];
__device__ __align__(16) __half g_ShP[(size_t)NTOT * 256];
__device__ __align__(16) __half g_SmP[(size_t)NTOT * 256];
__device__ __align__(16) __half g_HhP[(size_t)NTOT * 256];
__device__ __align__(16) __half g_HmP[(size_t)NTOT * 256];

// weight blocks: [plane2][row128][k16] fp16 = 4096 elems per block (planes: W1=C1*w, W2=(w-W1)*64)
__device__ __align__(16) __half g_WFG[(size_t)NBLK * 2 * 16 * 4096];
__device__ __align__(16) __half g_WRS[(size_t)NBLK * 8 * 4096];
__device__ __align__(16) __half g_WSK[(size_t)2 * 128 * 4096];
__device__ __align__(16) __half g_W1b[(size_t)2 * 16 * 4096];
__device__ __align__(16) __half g_W2b[(size_t)2 * 16 * 4096];
__device__ float g_Bsk[256];

// ---------------- helpers ----------------
__device__ __forceinline__ uint32_t smem_u32(const void* p) {
    uint32_t a;
    asm("{ .reg .u64 t; cvta.to.shared.u64 t, %1; cvt.u32.u64 %0, t; }" : "=r"(a) : "l"(p));
    return a;
}
// activation split: h = fp16(v), m = fp16(2^-6*h + (v - h)); reconstruct v = C1*h + m
__device__ __forceinline__ void msplit(float v, __half& h, __half& m) {
    h = __float2half(v);
    float hf = __half2float(h);
    m = __float2half(DELTA * hf + (v - hf));
}
// weight split: W1 = fp16(C1*v), W2 = fp16((v - W1)*64); then A1*W1 + A2*W2 ~= x*v
__device__ __forceinline__ void wsplit(float v, __half& w1, __half& w2) {
    w1 = __float2half(C1 * v);
    float w1f = __half2float(w1);
    w2 = __float2half((v - w1f) * 64.0f);
}
__device__ __forceinline__ float safe_tanh(float x) {
    float ax = fabsf(x);
    float e = __expf(-2.0f * ax);
    return copysignf((1.0f - e) / (1.0f + e), x);
}
__device__ __forceinline__ float sigmoidf_(float x) { return 1.0f / (1.0f + __expf(-x)); }

// ---------------- packing ----------------
__global__ void pack_fg(const float* __restrict__ Wf, const float* __restrict__ Wg) {
    int idx = blockIdx.x * blockDim.x + threadIdx.x;
    int kin = idx & 15, row = (idx >> 4) & 127, c = (idx >> 11) & 15;
    int nt = (idx >> 15) & 1, l = idx >> 16;
    int m = nt * 128 + row, ch = m >> 1, isg = m & 1;
    int tap = (c < 8) ? 1 : 0;
    int cin = (c & 7) * 16 + kin;
    float v = 0.f;
    if (ch < 120 && cin < 120) {
        const float* s = isg ? Wg : Wf;
        v = s[(((size_t)l * 120 + ch) * 120 + cin) * 2 + tap];
    }
    __half h, mo; wsplit(v, h, mo);
    __half* blk = g_WFG + ((size_t)((l * 2 + nt) * 16 + c)) * 4096;
    blk[row * 16 + kin] = h;
    blk[2048 + row * 16 + kin] = mo;
}

__global__ void pack_rs(const float* __restrict__ Wres) {
    int idx = blockIdx.x * blockDim.x + threadIdx.x;
    int kin = idx & 15, row = (idx >> 4) & 127, c = (idx >> 11) & 7, l = idx >> 14;
    int cin = c * 16 + kin;
    float v = (row < 120 && cin < 120) ? Wres[((size_t)l * 120 + row) * 120 + cin] : 0.f;
    __half h, mo; wsplit(v, h, mo);
    __half* blk = g_WRS + ((size_t)(l * 8 + c)) * 4096;
    blk[row * 16 + kin] = h;
    blk[2048 + row * 16 + kin] = mo;
}

__global__ void pack_sk(const float* __restrict__ Wskip, const float* __restrict__ bskip) {
    int idx = blockIdx.x * blockDim.x + threadIdx.x;
    int kin = idx & 15, row = (idx >> 4) & 127, c = (idx >> 11) & 127, nt = idx >> 18;
    int q = nt * 128 + row, lay = c >> 3, cin = (c & 7) * 16 + kin;
    float v = (q < 240 && cin < 120) ? Wskip[((size_t)lay * 240 + q) * 120 + cin] : 0.f;
    __half h, mo; wsplit(v, h, mo);
    __half* blk = g_WSK + ((size_t)(nt * 128 + c)) * 4096;
    blk[row * 16 + kin] = h;
    blk[2048 + row * 16 + kin] = mo;
    if (idx < 256) {
        float s = 0.f;
        if (idx < 240) for (int j = 0; j < NBLK; j++) s += bskip[j * 240 + idx];
        g_Bsk[idx] = s;
    }
}

__global__ void pack_h(const float* __restrict__ W1, const float* __restrict__ W2) {
    int idx = blockIdx.x * blockDim.x + threadIdx.x;
    int kin = idx & 15, row = (idx >> 4) & 127, c = (idx >> 11) & 15, nt = idx >> 15;
    int q = nt * 128 + row, k = c * 16 + kin;
    float v1 = (k < 240) ? W1[(size_t)q * 240 + k] : 0.f;
    float v2 = W2[(size_t)q * 256 + k];
    __half h, mo;
    __half* b1 = g_W1b + ((size_t)(nt * 16 + c)) * 4096;
    __half* b2 = g_W2b + ((size_t)(nt * 16 + c)) * 4096;
    wsplit(v1, h, mo); b1[row * 16 + kin] = h; b1[2048 + row * 16 + kin] = mo;
    wsplit(v2, h, mo); b2[row * 16 + kin] = h; b2[2048 + row * 16 + kin] = mo;
}

__global__ void init_kernel(const float* __restrict__ wave,
                            const float* __restrict__ W_in,
                            const float* __restrict__ b_in) {
    int idx = blockIdx.x * blockDim.x + threadIdx.x;
    int n = idx >> 7, c = idx & 127;
    float x = (c < 120) ? (W_in[c] * wave[n] + b_in[c]) : 0.f;
    __half h, m; msplit(x, h, m);
    g_Xh[0][idx] = h; g_Xm[0][idx] = m;
}

// ---------------- asm macros ----------------
#define CPA16(dst, src, sz) \
    asm volatile("cp.async.cg.shared.global [%0], [%1], 16, %2;" \
                 :: "r"(dst), "l"(src), "r"(sz) : "memory")
#define CP_COMMIT() asm volatile("cp.async.commit_group;" ::: "memory")
#define CP_WAIT1()  asm volatile("cp.async.wait_group 1;" ::: "memory")
#define CP_WAIT2()  asm volatile("cp.async.wait_group 2;" ::: "memory")

#define LDM4(rr, addr) \
    asm volatile("ldmatrix.sync.aligned.m8n8.x4.shared.b16 {%0,%1,%2,%3}, [%4];" \
                 : "=r"((rr)[0]), "=r"((rr)[1]), "=r"((rr)[2]), "=r"((rr)[3]) : "r"(addr))

#define MMA(cr, a, b0v, b1v) \
    asm volatile("mma.sync.aligned.m16n8k16.row.col.f32.f16.f16.f32 " \
                 "{%0,%1,%2,%3}, {%4,%5,%6,%7}, {%8,%9}, {%0,%1,%2,%3};" \
                 : "+f"((cr)[0]), "+f"((cr)[1]), "+f"((cr)[2]), "+f"((cr)[3]) \
                 : "r"((a)[0]), "r"((a)[1]), "r"((a)[2]), "r"((a)[3]), "r"(b0v), "r"(b1v))

// ---------------- fused FG + RES kernel: CTA 128(time) x 256(col), 512 thr ----------------
// Stage slot (36864B): Ah@0(6144) Am@6144 W1@12288(12288) W2@24576. 3 stages.
// z tile planes: zh@110592 (34816B), zm@110592+34816. pitch 272.
#define SLOT  36864u
#define ZOFF  110592u
#define ZPIT  272u
#define ZPL   34816u
#define FS_BYTES (110592 + 2 * 34816)

__global__ void __launch_bounds__(512, 1) fgres_kernel(int layer, int dil,
        const float* __restrict__ bf, const float* __restrict__ bg,
        const float* __restrict__ bres) {
    extern __shared__ __align__(16) char sm[];
    const int tid = threadIdx.x, lane = tid & 31, wid = tid >> 5;
    const int wn = wid >> 3, wc = wid & 7;      // 2 time-groups(64) x 8 col-groups(32)
    const int n0 = blockIdx.x * 128;
    const uint32_t smb = smem_u32(sm);

    const __half* Xrh = g_Xh[layer & 1];
    const __half* Xrm = g_Xm[layer & 1];
    __half* Xwh = g_Xh[(layer + 1) & 1];
    __half* Xwm = g_Xm[(layer + 1) & 1];
    const __half* Wb  = g_WFG + (size_t)layer * 2 * 16 * 4096;
    const __half* WRb = g_WRS + (size_t)layer * 8 * 4096;

    uint32_t offA[4], offB[2], offRB;
    {
        int rA = wn * 64 + (lane & 15);
        int cA = (lane >> 4) * 16;
#pragma unroll
        for (int i = 0; i < 4; i++) offA[i] = (uint32_t)((rA + i * 16) * 48 + cA);
        int rB = wc * 32 + (lane >> 4) * 8 + (lane & 7);
        int cB = ((lane >> 3) & 1) * 16;
        offB[0] = (uint32_t)(rB * 48 + cB);
        offB[1] = (uint32_t)((rB + 16) * 48 + cB);
        int rR = wc * 16 + (lane >> 4) * 8 + (lane & 7);
        offRB = (uint32_t)(rR * 48 + cB);
    }

    float acc[4][4][4];
#pragma unroll
    for (int i = 0; i < 4; i++)
#pragma unroll
        for (int j = 0; j < 4; j++)
#pragma unroll
            for (int k = 0; k < 4; k++) acc[i][j][k] = 0.f;

#define FSTAGE(cc, s) do {                                                        \
        {   /* A: 2 planes x 128 rows x 32B = 8KB, exactly 1 op/thread */         \
            int p = tid >> 8, r = (tid >> 1) & 127, hh = tid & 1;                 \
            int na = n0 + r, nn = na, sz = 16, ch0;                               \
            if ((cc) < 8) ch0 = (cc) * 16;                                        \
            else {                                                                \
                ch0 = ((cc) - 8) * 16;                                            \
                int t = na & (T_LEN - 1);                                         \
                if (t >= dil) nn = na - dil; else sz = 0;                         \
            }                                                                     \
            uint32_t d = smb + (s) * SLOT + p * 6144u + r * 48u + hh * 16u;       \
            const __half* gp = (p ? Xrm : Xrh) + (size_t)nn * 128 + ch0 + hh * 8; \
            CPA16(d, gp, sz);                                                     \
        }                                                                         \
        _Pragma("unroll")                                                         \
        for (int ii = 0; ii < 2; ii++) {   /* W: 2 planes x 256 rows x 32B = 16KB */ \
            int u = tid + ii * 512, p = (u >> 9) & 1, r = (u >> 1) & 255, hh = u & 1; \
            uint32_t d = smb + (s) * SLOT + 12288u + p * 12288u + r * 48u + hh * 16u; \
            const __half* sp = Wb + ((size_t)((r >> 7) * 16 + (cc))) * 4096       \
                               + p * 2048 + (r & 127) * 16 + hh * 8;              \
            CPA16(d, sp, 16);                                                     \
        }                                                                         \
    } while (0)

    FSTAGE(0, 0); CP_COMMIT();
    FSTAGE(1, 1); CP_COMMIT();

#pragma unroll 1
    for (int c = 0; c < 16; c++) {
        CP_WAIT1();
        __syncthreads();
        if (c + 2 < 16) FSTAGE(c + 2, (c + 2) % 3);
        CP_COMMIT();

        const uint32_t base = smb + (uint32_t)(c % 3) * SLOT;
        uint32_t Af[4][4], Bf[2][4];
        // plane 1: A1 x W1
#pragma unroll
        for (int i = 0; i < 4; i++) LDM4(Af[i], base + offA[i]);
        LDM4(Bf[0], base + 12288u + offB[0]);
        LDM4(Bf[1], base + 12288u + offB[1]);
#pragma unroll
        for (int i = 0; i < 4; i++)
#pragma unroll
            for (int j = 0; j < 4; j++)
                MMA(acc[i][j], Af[i], Bf[j >> 1][(j & 1) * 2], Bf[j >> 1][(j & 1) * 2 + 1]);
        // plane 2: A2 x W2 (reuse fragment arrays)
#pragma unroll
        for (int i = 0; i < 4; i++) LDM4(Af[i], base + 6144u + offA[i]);
        LDM4(Bf[0], base + 24576u + offB[0]);
        LDM4(Bf[1], base + 24576u + offB[1]);
#pragma unroll
        for (int i = 0; i < 4; i++)
#pragma unroll
            for (int j = 0; j < 4; j++)
                MMA(acc[i][j], Af[i], Bf[j >> 1][(j & 1) * 2], Bf[j >> 1][(j & 1) * 2 + 1]);
    }
#undef FSTAGE

    // RES W prefetch (overlaps z epilogue). Stage: W1@0 (128x48), W2@6144.
#define RSTAGE(rc, s) do {                                                        \
        int p = tid >> 8, r = (tid >> 1) & 127, hh = tid & 1;                     \
        uint32_t d = smb + (s) * SLOT + p * 6144u + r * 48u + hh * 16u;           \
        const __half* sp = WRb + (size_t)(rc) * 4096 + p * 2048 + r * 16 + hh * 8; \
        CPA16(d, sp, 16);                                                         \
    } while (0)

    __syncthreads();   // all FG reads of stage slots done before RES W overwrites
    RSTAGE(0, 0); CP_COMMIT();
    RSTAGE(1, 1); CP_COMMIT();

    // ---- epilogue 1: z = tanh(f)*sigmoid(g); split-store to SMEM z planes + gmem ----
#pragma unroll
    for (int j = 0; j < 4; j++) {
        int c0 = wc * 32 + j * 8 + (lane & 3) * 2;
        int ch = c0 >> 1;
        float bfv = 0.f, bgv = 0.f;
        if (ch < 120) { bfv = bf[layer * 120 + ch]; bgv = bg[layer * 120 + ch]; }
#pragma unroll
        for (int i = 0; i < 4; i++)
#pragma unroll
            for (int h = 0; h < 2; h++) {
                int row = wn * 64 + i * 16 + h * 8 + (lane >> 2);
                float f = acc[i][j][h * 2] + bfv;
                float g = acc[i][j][h * 2 + 1] + bgv;
                float z = safe_tanh(f) * sigmoidf_(g);
                __half zh, zm; msplit(z, zh, zm);
                *reinterpret_cast<__half*>(sm + ZOFF + row * ZPIT + ch * 2) = zh;
                *reinterpret_cast<__half*>(sm + ZOFF + ZPL + row * ZPIT + ch * 2) = zm;
                size_t off = (size_t)layer * NTOT * 128 + (size_t)(n0 + row) * 128 + ch;
                g_ZhP[off] = zh; g_ZmP[off] = zm;
            }
    }

    // ---- RES GEMM: res[128t x 128ch] = z @ Wres^T (z from SMEM planes) ----
    float racc[4][2][4];
#pragma unroll
    for (int i = 0; i < 4; i++)
#pragma unroll
        for (int j = 0; j < 2; j++)
#pragma unroll
            for (int k = 0; k < 4; k++) racc[i][j][k] = 0.f;

#pragma unroll 1
    for (int rc = 0; rc < 8; rc++) {
        CP_WAIT1();
        __syncthreads();
        if (rc + 2 < 8) RSTAGE(rc + 2, (rc + 2) % 3);
        CP_COMMIT();

        const uint32_t base = smb + (uint32_t)(rc % 3) * SLOT;
        uint32_t Zf[4][4], RB[4];
        uint32_t zk = (uint32_t)(rc * 32) + (lane >> 4) * 16;
        // plane 1
#pragma unroll
        for (int i = 0; i < 4; i++) {
            uint32_t zr = smb + ZOFF + (wn * 64 + i * 16 + (lane & 15)) * ZPIT + zk;
            LDM4(Zf[i], zr);
        }
        LDM4(RB, base + offRB);
#pragma unroll
        for (int i = 0; i < 4; i++)
#pragma unroll
            for (int j = 0; j < 2; j++)
                MMA(racc[i][j], Zf[i], RB[j * 2], RB[j * 2 + 1]);
        // plane 2
#pragma unroll
        for (int i = 0; i < 4; i++) {
            uint32_t zr = smb + ZOFF + ZPL + (wn * 64 + i * 16 + (lane & 15)) * ZPIT + zk;
            LDM4(Zf[i], zr);
        }
        LDM4(RB, base + 6144u + offRB);
#pragma unroll
        for (int i = 0; i < 4; i++)
#pragma unroll
            for (int j = 0; j < 2; j++)
                MMA(racc[i][j], Zf[i], RB[j * 2], RB[j * 2 + 1]);
    }
#undef RSTAGE

    // ---- epilogue 2: X_next = (C1*Xh + Xm) + res + bres, split-stored ----
#pragma unroll
    for (int j = 0; j < 2; j++) {
        int col = wc * 16 + j * 8 + (lane & 3) * 2;
        if (col < 120) {
            float bv0 = bres[layer * 120 + col];
            float bv1 = bres[layer * 120 + col + 1];
#pragma unroll
            for (int i = 0; i < 4; i++)
#pragma unroll
                for (int h = 0; h < 2; h++) {
                    int row = n0 + wn * 64 + i * 16 + h * 8 + (lane >> 2);
                    size_t off = (size_t)row * 128 + col;
                    __half2 xh = *reinterpret_cast<const __half2*>(Xrh + off);
                    __half2 xm = *reinterpret_cast<const __half2*>(Xrm + off);
                    float x0 = C1 * __half2float(xh.x) + __half2float(xm.x)
                             + racc[i][j][h * 2] + bv0;
                    float x1 = C1 * __half2float(xh.y) + __half2float(xm.y)
                             + racc[i][j][h * 2 + 1] + bv1;
                    __half h0, m0, h1, m1;
                    msplit(x0, h0, m0); msplit(x1, h1, m1);
                    __half2 hp; hp.x = h0; hp.y = h1;
                    __half2 mp; mp.x = m0; mp.y = m1;
                    *reinterpret_cast<__half2*>(Xwh + off) = hp;
                    *reinterpret_cast<__half2*>(Xwm + off) = mp;
                }
        }
    }
}

// ---------------- generic GEMM (SKIP / H1 / H2): CTA 128 x 256, 512 thr, 4 stages ----------------
template<int MODE, int NCH>
__global__ void __launch_bounds__(512, 1) mma_kernel(const float* __restrict__ bA,
                                                     float* __restrict__ dout) {
    extern __shared__ __align__(16) char sm[];
    const int tid = threadIdx.x, lane = tid & 31, wid = tid >> 5;
    const int wn = wid >> 3, wc = wid & 7;
    const int n0 = blockIdx.x * 128;
    const uint32_t smb = smem_u32(sm);

    const __half *Wfam, *APh, *APm;
    int NB, CHW;
    if (MODE == 2)      { Wfam = g_WSK; NB = 128; APh = g_ZhP; APm = g_ZmP; CHW = 128; }
    else if (MODE == 3) { Wfam = g_W1b; NB = 16;  APh = g_ShP; APm = g_SmP; CHW = 256; }
    else                { Wfam = g_W2b; NB = 16;  APh = g_HhP; APm = g_HmP; CHW = 256; }

    uint32_t offA[4], offB[2];
    {
        int rA = wn * 64 + (lane & 15);
        int cA = (lane >> 4) * 16;
#pragma unroll
        for (int i = 0; i < 4; i++) offA[i] = (uint32_t)((rA + i * 16) * 48 + cA);
        int rB = wc * 32 + (lane >> 4) * 8 + (lane & 7);
        int cB = ((lane >> 3) & 1) * 16;
        offB[0] = (uint32_t)(rB * 48 + cB);
        offB[1] = (uint32_t)((rB + 16) * 48 + cB);
    }

    float acc[4][4][4];
#pragma unroll
    for (int i = 0; i < 4; i++)
#pragma unroll
        for (int j = 0; j < 4; j++)
#pragma unroll
            for (int k = 0; k < 4; k++) acc[i][j][k] = 0.f;

#define STAGE(cc, s) do {                                                         \
        {   /* A: 2 planes, 1 op/thread */                                        \
            int p = tid >> 8, r = (tid >> 1) & 127, hh = tid & 1;                 \
            int ch0; const __half* ap = p ? APm : APh;                            \
            if (MODE == 2) {                                                      \
                ch0 = ((cc) & 7) * 16;                                            \
                ap += (size_t)((cc) >> 3) * NTOT * 128;                           \
            } else ch0 = (cc) * 16;                                               \
            uint32_t d = smb + (s) * SLOT + p * 6144u + r * 48u + hh * 16u;       \
            CPA16(d, ap + (size_t)(n0 + r) * CHW + ch0 + hh * 8, 16);             \
        }                                                                         \
        _Pragma("unroll")                                                         \
        for (int ii = 0; ii < 2; ii++) {                                          \
            int u = tid + ii * 512, p = (u >> 9) & 1, r = (u >> 1) & 255, hh = u & 1; \
            uint32_t d = smb + (s) * SLOT + 12288u + p * 12288u + r * 48u + hh * 16u; \
            const __half* sp = Wfam + ((size_t)((r >> 7) * NB + (cc))) * 4096     \
                               + p * 2048 + (r & 127) * 16 + hh * 8;              \
            CPA16(d, sp, 16);                                                     \
        }                                                                         \
    } while (0)

    STAGE(0, 0); CP_COMMIT();
    STAGE(1, 1); CP_COMMIT();
    STAGE(2, 2); CP_COMMIT();

#pragma unroll 1
    for (int c = 0; c < NCH; c++) {
        CP_WAIT2();
        __syncthreads();
        if (c + 3 < NCH) STAGE(c + 3, (c + 3) & 3);
        CP_COMMIT();

        const uint32_t base = smb + (uint32_t)(c & 3) * SLOT;
        uint32_t Af[4][4], Bf[2][4];
        // plane 1
#pragma unroll
        for (int i = 0; i < 4; i++) LDM4(Af[i], base + offA[i]);
        LDM4(Bf[0], base + 12288u + offB[0]);
        LDM4(Bf[1], base + 12288u + offB[1]);
#pragma unroll
        for (int i = 0; i < 4; i++)
#pragma unroll
            for (int j = 0; j < 4; j++)
                MMA(acc[i][j], Af[i], Bf[j >> 1][(j & 1) * 2], Bf[j >> 1][(j & 1) * 2 + 1]);
        // plane 2
#pragma unroll
        for (int i = 0; i < 4; i++) LDM4(Af[i], base + 6144u + offA[i]);
        LDM4(Bf[0], base + 24576u + offB[0]);
        LDM4(Bf[1], base + 24576u + offB[1]);
#pragma unroll
        for (int i = 0; i < 4; i++)
#pragma unroll
            for (int j = 0; j < 4; j++)
                MMA(acc[i][j], Af[i], Bf[j >> 1][(j & 1) * 2], Bf[j >> 1][(j & 1) * 2 + 1]);
    }
#undef STAGE

#pragma unroll
    for (int j = 0; j < 4; j++) {
        const int col = wc * 32 + j * 8 + (lane & 3) * 2;
        float bv0, bv1;
        if (MODE == 2) { bv0 = g_Bsk[col]; bv1 = g_Bsk[col + 1]; }
        else           { bv0 = bA[col]; bv1 = bA[col + 1]; }
#pragma unroll
        for (int i = 0; i < 4; i++)
#pragma unroll
            for (int h = 0; h < 2; h++) {
                int na = n0 + wn * 64 + i * 16 + h * 8 + (lane >> 2);
                float v0 = acc[i][j][h * 2] + bv0;
                float v1 = acc[i][j][h * 2 + 1] + bv1;
                if (MODE == 2 || MODE == 3) {
                    float r0 = fmaxf(v0, 0.f), r1 = fmaxf(v1, 0.f);
                    __half h0, m0, h1, m1;
                    msplit(r0, h0, m0); msplit(r1, h1, m1);
                    __half2 hp; hp.x = h0; hp.y = h1;
                    __half2 mp; mp.x = m0; mp.y = m1;
                    __half* Oh = (MODE == 2) ? g_ShP : g_HhP;
                    __half* Om = (MODE == 2) ? g_SmP : g_HmP;
                    *reinterpret_cast<__half2*>(Oh + (size_t)na * 256 + col) = hp;
                    *reinterpret_cast<__half2*>(Om + (size_t)na * 256 + col) = mp;
                } else {
                    int b = na >> 14, t = na & (T_LEN - 1);
                    dout[((size_t)b * 256 + col) * T_LEN + t]     = v0;
                    dout[((size_t)b * 256 + col + 1) * T_LEN + t] = v1;
                }
            }
    }
}

// ---------------- launch ----------------
extern "C" void kernel_launch(void* const* d_in, const int* in_sizes, int n_in,
                              void* d_out, int out_size) {
    const float* wave  = (const float*)d_in[0];
    const float* W_in  = (const float*)d_in[1];
    const float* b_in  = (const float*)d_in[2];
    const float* Wf    = (const float*)d_in[3];
    const float* bf    = (const float*)d_in[4];
    const float* Wg    = (const float*)d_in[5];
    const float* bg    = (const float*)d_in[6];
    const float* Wres  = (const float*)d_in[7];
    const float* bres  = (const float*)d_in[8];
    const float* Wskip = (const float*)d_in[9];
    const float* bskip = (const float*)d_in[10];
    const float* W1    = (const float*)d_in[11];
    const float* b1    = (const float*)d_in[12];
    const float* W2    = (const float*)d_in[13];
    const float* b2    = (const float*)d_in[14];
    float* out = (float*)d_out;

    const int GS = 4 * SLOT;   // 147456 for generic kernels
    cudaFuncSetAttribute(fgres_kernel, cudaFuncAttributeMaxDynamicSharedMemorySize, FS_BYTES);
    cudaFuncSetAttribute(mma_kernel<2, 128>, cudaFuncAttributeMaxDynamicSharedMemorySize, GS);
    cudaFuncSetAttribute(mma_kernel<3, 16>,  cudaFuncAttributeMaxDynamicSharedMemorySize, GS);
    cudaFuncSetAttribute(mma_kernel<4, 16>,  cudaFuncAttributeMaxDynamicSharedMemorySize, GS);

    pack_fg<<<16 * 2 * 16 * 2048 / 256, 256>>>(Wf, Wg);
    pack_rs<<<16 * 8 * 2048 / 256, 256>>>(Wres);
    pack_sk<<<2 * 128 * 2048 / 256, 256>>>(Wskip, bskip);
    pack_h <<<2 * 16 * 2048 / 256, 256>>>(W1, W2);
    init_kernel<<<(size_t)NTOT * 128 / 256, 256>>>(wave, W_in, b_in);

    static const int dil[NBLK] = {1, 2, 4, 8, 16, 32, 64, 128,
                                  1, 2, 4, 8, 16, 32, 64, 128};

    for (int i = 0; i < NBLK; i++)
        fgres_kernel<<<NTOT / 128, 512, FS_BYTES>>>(i, dil[i], bf, bg, bres);

    mma_kernel<2, 128><<<NTOT / 128, 512, GS>>>(nullptr, nullptr);  // batched skip
    mma_kernel<3, 16><<<NTOT / 128, 512, GS>>>(b1, nullptr);        // head1
    mma_kernel<4, 16><<<NTOT / 128, 512, GS>>>(b2, out);            // head2
}

// round 13
// speedup vs baseline: 2.1049x; 1.1695x over previous
#include <cuda_runtime.h>
#include <cuda_fp16.h>
#include <cstdint>
#include <cstddef>

#define T_LEN 16384
#define NTOT  131072
#define NBLK  16

#define DELTA 0.015625f     // 2^-6
#define C1    0.984375f     // 1 - 2^-6

// ---------------- activations, time-major [n][ch] ----------------
__device__ __align__(16) __half g_Xh[2][(size_t)NTOT * 128];
__device__ __align__(16) __half g_Xm[2][(size_t)NTOT * 128];
__device__ __align__(16) __half g_Z [(size_t)NBLK * NTOT * 128];  // single fp16 (skip input)
__device__ __align__(16) __half g_ShP[(size_t)NTOT * 256];
__device__ __align__(16) __half g_SmP[(size_t)NTOT * 256];
__device__ __align__(16) __half g_HhP[(size_t)NTOT * 256];
__device__ __align__(16) __half g_HmP[(size_t)NTOT * 256];

// weight blocks. 2-plane: [plane2][row128][k16] (W1=C1*w, W2=(w-W1)*64). skip: single plane.
__device__ __align__(16) __half g_WFG[(size_t)NBLK * 2 * 16 * 4096];
__device__ __align__(16) __half g_WRS[(size_t)NBLK * 8 * 4096];
__device__ __align__(16) __half g_WSK[(size_t)2 * 128 * 2048];    // single fp16
__device__ __align__(16) __half g_W1b[(size_t)2 * 16 * 4096];
__device__ __align__(16) __half g_W2b[(size_t)2 * 16 * 4096];
__device__ float g_Bsk[256];

// ---------------- helpers ----------------
__device__ __forceinline__ uint32_t smem_u32(const void* p) {
    uint32_t a;
    asm("{ .reg .u64 t; cvta.to.shared.u64 t, %1; cvt.u32.u64 %0, t; }" : "=r"(a) : "l"(p));
    return a;
}
// activation split: h = fp16(v), m = fp16(2^-6*h + (v-h)); reconstruct v = C1*h + m
__device__ __forceinline__ void msplit(float v, __half& h, __half& m) {
    h = __float2half(v);
    float hf = __half2float(h);
    m = __float2half(DELTA * hf + (v - hf));
}
// weight split: W1 = fp16(C1*v), W2 = fp16((v-W1)*64); A1*W1 + A2*W2 ~= x*v
__device__ __forceinline__ void wsplit(float v, __half& w1, __half& w2) {
    w1 = __float2half(C1 * v);
    float w1f = __half2float(w1);
    w2 = __float2half((v - w1f) * 64.0f);
}
__device__ __forceinline__ float safe_tanh(float x) {
    float ax = fabsf(x);
    float e = __expf(-2.0f * ax);
    return copysignf((1.0f - e) / (1.0f + e), x);
}
__device__ __forceinline__ float sigmoidf_(float x) { return 1.0f / (1.0f + __expf(-x)); }

// ---------------- packing ----------------
__global__ void pack_fg(const float* __restrict__ Wf, const float* __restrict__ Wg) {
    int idx = blockIdx.x * blockDim.x + threadIdx.x;
    int kin = idx & 15, row = (idx >> 4) & 127, c = (idx >> 11) & 15;
    int nt = (idx >> 15) & 1, l = idx >> 16;
    int m = nt * 128 + row, ch = m >> 1, isg = m & 1;
    int tap = (c < 8) ? 1 : 0;
    int cin = (c & 7) * 16 + kin;
    float v = 0.f;
    if (ch < 120 && cin < 120) {
        const float* s = isg ? Wg : Wf;
        v = s[(((size_t)l * 120 + ch) * 120 + cin) * 2 + tap];
    }
    __half h, mo; wsplit(v, h, mo);
    __half* blk = g_WFG + ((size_t)((l * 2 + nt) * 16 + c)) * 4096;
    blk[row * 16 + kin] = h;
    blk[2048 + row * 16 + kin] = mo;
}

__global__ void pack_rs(const float* __restrict__ Wres) {
    int idx = blockIdx.x * blockDim.x + threadIdx.x;
    int kin = idx & 15, row = (idx >> 4) & 127, c = (idx >> 11) & 7, l = idx >> 14;
    int cin = c * 16 + kin;
    float v = (row < 120 && cin < 120) ? Wres[((size_t)l * 120 + row) * 120 + cin] : 0.f;
    __half h, mo; wsplit(v, h, mo);
    __half* blk = g_WRS + ((size_t)(l * 8 + c)) * 4096;
    blk[row * 16 + kin] = h;
    blk[2048 + row * 16 + kin] = mo;
}

__global__ void pack_sk(const float* __restrict__ Wskip, const float* __restrict__ bskip) {
    int idx = blockIdx.x * blockDim.x + threadIdx.x;   // 2*128*2048
    int kin = idx & 15, row = (idx >> 4) & 127, c = (idx >> 11) & 127, nt = idx >> 18;
    int q = nt * 128 + row, lay = c >> 3, cin = (c & 7) * 16 + kin;
    float v = (q < 240 && cin < 120) ? Wskip[((size_t)lay * 240 + q) * 120 + cin] : 0.f;
    g_WSK[((size_t)(nt * 128 + c)) * 2048 + row * 16 + kin] = __float2half(v);
    if (idx < 256) {
        float s = 0.f;
        if (idx < 240) for (int j = 0; j < NBLK; j++) s += bskip[j * 240 + idx];
        g_Bsk[idx] = s;
    }
}

__global__ void pack_h(const float* __restrict__ W1, const float* __restrict__ W2) {
    int idx = blockIdx.x * blockDim.x + threadIdx.x;
    int kin = idx & 15, row = (idx >> 4) & 127, c = (idx >> 11) & 15, nt = idx >> 15;
    int q = nt * 128 + row, k = c * 16 + kin;
    float v1 = (k < 240) ? W1[(size_t)q * 240 + k] : 0.f;
    float v2 = W2[(size_t)q * 256 + k];
    __half h, mo;
    __half* b1 = g_W1b + ((size_t)(nt * 16 + c)) * 4096;
    __half* b2 = g_W2b + ((size_t)(nt * 16 + c)) * 4096;
    wsplit(v1, h, mo); b1[row * 16 + kin] = h; b1[2048 + row * 16 + kin] = mo;
    wsplit(v2, h, mo); b2[row * 16 + kin] = h; b2[2048 + row * 16 + kin] = mo;
}

__global__ void init_kernel(const float* __restrict__ wave,
                            const float* __restrict__ W_in,
                            const float* __restrict__ b_in) {
    int idx = blockIdx.x * blockDim.x + threadIdx.x;
    int n = idx >> 7, c = idx & 127;
    float x = (c < 120) ? (W_in[c] * wave[n] + b_in[c]) : 0.f;
    __half h, m; msplit(x, h, m);
    g_Xh[0][idx] = h; g_Xm[0][idx] = m;
}

// ---------------- asm macros ----------------
#define CPA16(dst, src, sz) \
    asm volatile("cp.async.cg.shared.global [%0], [%1], 16, %2;" \
                 :: "r"(dst), "l"(src), "r"(sz) : "memory")
#define CP_COMMIT() asm volatile("cp.async.commit_group;" ::: "memory")
#define CP_WAIT2()  asm volatile("cp.async.wait_group 2;" ::: "memory")

#define LDM4(rr, addr) \
    asm volatile("ldmatrix.sync.aligned.m8n8.x4.shared.b16 {%0,%1,%2,%3}, [%4];" \
                 : "=r"((rr)[0]), "=r"((rr)[1]), "=r"((rr)[2]), "=r"((rr)[3]) : "r"(addr))

#define MMA(cr, a, b0v, b1v) \
    asm volatile("mma.sync.aligned.m16n8k16.row.col.f32.f16.f16.f32 " \
                 "{%0,%1,%2,%3}, {%4,%5,%6,%7}, {%8,%9}, {%0,%1,%2,%3};" \
                 : "+f"((cr)[0]), "+f"((cr)[1]), "+f"((cr)[2]), "+f"((cr)[3]) \
                 : "r"((a)[0]), "r"((a)[1]), "r"((a)[2]), "r"((a)[3]), "r"(b0v), "r"(b1v))

// ---------------- fused FG + RES kernel: CTA 128(time) x 256(col), 512 thr, 4 stages ----------------
// Stage slot (36864B): Ah@0(6144) Am@6144 W1@12288(12288) W2@24576.
// z tile planes: zh@147456 (34816B), zm@+34816. pitch 272.
#define SLOT  36864u
#define ZOFF  147456u
#define ZPIT  272u
#define ZPL   34816u
#define FS_BYTES (147456 + 2 * 34816)   // 217088

__global__ void __launch_bounds__(512, 1) fgres_kernel(int layer, int dil,
        const float* __restrict__ bf, const float* __restrict__ bg,
        const float* __restrict__ bres) {
    extern __shared__ __align__(16) char sm[];
    const int tid = threadIdx.x, lane = tid & 31, wid = tid >> 5;
    const int wn = wid >> 3, wc = wid & 7;      // 2 time-groups(64) x 8 col-groups(32)
    const int n0 = blockIdx.x * 128;
    const uint32_t smb = smem_u32(sm);

    const __half* Xrh = g_Xh[layer & 1];
    const __half* Xrm = g_Xm[layer & 1];
    __half* Xwh = g_Xh[(layer + 1) & 1];
    __half* Xwm = g_Xm[(layer + 1) & 1];
    const __half* Wb  = g_WFG + (size_t)layer * 2 * 16 * 4096;
    const __half* WRb = g_WRS + (size_t)layer * 8 * 4096;

    uint32_t offA[4], offB[2], offRB;
    {
        int rA = wn * 64 + (lane & 15);
        int cA = (lane >> 4) * 16;
#pragma unroll
        for (int i = 0; i < 4; i++) offA[i] = (uint32_t)((rA + i * 16) * 48 + cA);
        int rB = wc * 32 + (lane >> 4) * 8 + (lane & 7);
        int cB = ((lane >> 3) & 1) * 16;
        offB[0] = (uint32_t)(rB * 48 + cB);
        offB[1] = (uint32_t)((rB + 16) * 48 + cB);
        int rR = wc * 16 + (lane >> 4) * 8 + (lane & 7);
        offRB = (uint32_t)(rR * 48 + cB);
    }

    float acc[4][4][4];
#pragma unroll
    for (int i = 0; i < 4; i++)
#pragma unroll
        for (int j = 0; j < 4; j++)
#pragma unroll
            for (int k = 0; k < 4; k++) acc[i][j][k] = 0.f;

#define FSTAGE(cc, s) do {                                                        \
        {   /* A: 2 planes x 128 rows x 32B = 8KB, 1 op/thread */                 \
            int p = tid >> 8, r = (tid >> 1) & 127, hh = tid & 1;                 \
            int na = n0 + r, nn = na, sz = 16, ch0;                               \
            if ((cc) < 8) ch0 = (cc) * 16;                                        \
            else {                                                                \
                ch0 = ((cc) - 8) * 16;                                            \
                int t = na & (T_LEN - 1);                                         \
                if (t >= dil) nn = na - dil; else sz = 0;                         \
            }                                                                     \
            uint32_t d = smb + (s) * SLOT + p * 6144u + r * 48u + hh * 16u;       \
            const __half* gp = (p ? Xrm : Xrh) + (size_t)nn * 128 + ch0 + hh * 8; \
            CPA16(d, gp, sz);                                                     \
        }                                                                         \
        _Pragma("unroll")                                                         \
        for (int ii = 0; ii < 2; ii++) {   /* W: 2 planes x 256 rows x 32B = 16KB */ \
            int u = tid + ii * 512, p = (u >> 9) & 1, r = (u >> 1) & 255, hh = u & 1; \
            uint32_t d = smb + (s) * SLOT + 12288u + p * 12288u + r * 48u + hh * 16u; \
            const __half* sp = Wb + ((size_t)((r >> 7) * 16 + (cc))) * 4096       \
                               + p * 2048 + (r & 127) * 16 + hh * 8;              \
            CPA16(d, sp, 16);                                                     \
        }                                                                         \
    } while (0)

    FSTAGE(0, 0); CP_COMMIT();
    FSTAGE(1, 1); CP_COMMIT();
    FSTAGE(2, 2); CP_COMMIT();

#pragma unroll 1
    for (int c = 0; c < 16; c++) {
        CP_WAIT2();
        __syncthreads();
        if (c + 3 < 16) FSTAGE(c + 3, (c + 3) & 3);
        CP_COMMIT();

        const uint32_t base = smb + (uint32_t)(c & 3) * SLOT;
        uint32_t A1[4][4], A2[4][4], Bf[2][4];
#pragma unroll
        for (int i = 0; i < 4; i++) {
            LDM4(A1[i], base + offA[i]);
            LDM4(A2[i], base + 6144u + offA[i]);
        }
        LDM4(Bf[0], base + 12288u + offB[0]);
        LDM4(Bf[1], base + 12288u + offB[1]);
#pragma unroll
        for (int i = 0; i < 4; i++)
#pragma unroll
            for (int j = 0; j < 4; j++)
                MMA(acc[i][j], A1[i], Bf[j >> 1][(j & 1) * 2], Bf[j >> 1][(j & 1) * 2 + 1]);
        LDM4(Bf[0], base + 24576u + offB[0]);
        LDM4(Bf[1], base + 24576u + offB[1]);
#pragma unroll
        for (int i = 0; i < 4; i++)
#pragma unroll
            for (int j = 0; j < 4; j++)
                MMA(acc[i][j], A2[i], Bf[j >> 1][(j & 1) * 2], Bf[j >> 1][(j & 1) * 2 + 1]);
    }
#undef FSTAGE

    // RES W prefetch (slots 0..2 are no longer being read; slot 3 handled in loop).
#define RSTAGE(rc, s) do {                                                        \
        int p = tid >> 8, r = (tid >> 1) & 127, hh = tid & 1;                     \
        uint32_t d = smb + (s) * SLOT + p * 6144u + r * 48u + hh * 16u;           \
        const __half* sp = WRb + (size_t)(rc) * 4096 + p * 2048 + r * 16 + hh * 8; \
        CPA16(d, sp, 16);                                                         \
    } while (0)

    __syncthreads();   // all FG reads of all slots done before RES W overwrites
    RSTAGE(0, 0); CP_COMMIT();
    RSTAGE(1, 1); CP_COMMIT();
    RSTAGE(2, 2); CP_COMMIT();

    // ---- epilogue 1: z = tanh(f)*sigmoid(g); 2-plane to SMEM, single-plane to gmem ----
#pragma unroll
    for (int j = 0; j < 4; j++) {
        int c0 = wc * 32 + j * 8 + (lane & 3) * 2;
        int ch = c0 >> 1;
        float bfv = 0.f, bgv = 0.f;
        if (ch < 120) { bfv = bf[layer * 120 + ch]; bgv = bg[layer * 120 + ch]; }
#pragma unroll
        for (int i = 0; i < 4; i++)
#pragma unroll
            for (int h = 0; h < 2; h++) {
                int row = wn * 64 + i * 16 + h * 8 + (lane >> 2);
                float f = acc[i][j][h * 2] + bfv;
                float g = acc[i][j][h * 2 + 1] + bgv;
                float z = safe_tanh(f) * sigmoidf_(g);
                __half zh, zm; msplit(z, zh, zm);
                *reinterpret_cast<__half*>(sm + ZOFF + row * ZPIT + ch * 2) = zh;
                *reinterpret_cast<__half*>(sm + ZOFF + ZPL + row * ZPIT + ch * 2) = zm;
                g_Z[(size_t)layer * NTOT * 128 + (size_t)(n0 + row) * 128 + ch] =
                    __float2half(z);
            }
    }

    // ---- RES GEMM: res[128t x 128ch] = z @ Wres^T (z from SMEM planes) ----
    float racc[4][2][4];
#pragma unroll
    for (int i = 0; i < 4; i++)
#pragma unroll
        for (int j = 0; j < 2; j++)
#pragma unroll
            for (int k = 0; k < 4; k++) racc[i][j][k] = 0.f;

#pragma unroll 1
    for (int rc = 0; rc < 8; rc++) {
        CP_WAIT2();
        __syncthreads();
        if (rc + 3 < 8) RSTAGE(rc + 3, (rc + 3) & 3);
        CP_COMMIT();

        const uint32_t base = smb + (uint32_t)(rc & 3) * SLOT;
        uint32_t Z1[4][4], Z2[4][4], RB[4];
        uint32_t zk = (uint32_t)(rc * 32) + (lane >> 4) * 16;
#pragma unroll
        for (int i = 0; i < 4; i++) {
            uint32_t zr = smb + ZOFF + (wn * 64 + i * 16 + (lane & 15)) * ZPIT + zk;
            LDM4(Z1[i], zr);
            LDM4(Z2[i], zr + ZPL);
        }
        LDM4(RB, base + offRB);
#pragma unroll
        for (int i = 0; i < 4; i++)
#pragma unroll
            for (int j = 0; j < 2; j++)
                MMA(racc[i][j], Z1[i], RB[j * 2], RB[j * 2 + 1]);
        LDM4(RB, base + 6144u + offRB);
#pragma unroll
        for (int i = 0; i < 4; i++)
#pragma unroll
            for (int j = 0; j < 2; j++)
                MMA(racc[i][j], Z2[i], RB[j * 2], RB[j * 2 + 1]);
    }
#undef RSTAGE

    // ---- epilogue 2: X_next = (C1*Xh + Xm) + res + bres, split-stored ----
#pragma unroll
    for (int j = 0; j < 2; j++) {
        int col = wc * 16 + j * 8 + (lane & 3) * 2;
        if (col < 120) {
            float bv0 = bres[layer * 120 + col];
            float bv1 = bres[layer * 120 + col + 1];
#pragma unroll
            for (int i = 0; i < 4; i++)
#pragma unroll
                for (int h = 0; h < 2; h++) {
                    int row = n0 + wn * 64 + i * 16 + h * 8 + (lane >> 2);
                    size_t off = (size_t)row * 128 + col;
                    __half2 xh = *reinterpret_cast<const __half2*>(Xrh + off);
                    __half2 xm = *reinterpret_cast<const __half2*>(Xrm + off);
                    float x0 = C1 * __half2float(xh.x) + __half2float(xm.x)
                             + racc[i][j][h * 2] + bv0;
                    float x1 = C1 * __half2float(xh.y) + __half2float(xm.y)
                             + racc[i][j][h * 2 + 1] + bv1;
                    __half h0, m0, h1, m1;
                    msplit(x0, h0, m0); msplit(x1, h1, m1);
                    __half2 hp; hp.x = h0; hp.y = h1;
                    __half2 mp; mp.x = m0; mp.y = m1;
                    *reinterpret_cast<__half2*>(Xwh + off) = hp;
                    *reinterpret_cast<__half2*>(Xwm + off) = mp;
                }
        }
    }
}

// ---------------- generic GEMM: CTA 128 x 256, 512 thr, 4 stages ----------------
// MODE 2 = SKIP (PLANES=1, single fp16 z & w), MODE 3 = H1, MODE 4 = H2 (PLANES=2).
template<int MODE, int NCH, int PLANES>
__global__ void __launch_bounds__(512, 1) mma_kernel(const float* __restrict__ bA,
                                                     float* __restrict__ dout) {
    extern __shared__ __align__(16) char sm[];
    const int tid = threadIdx.x, lane = tid & 31, wid = tid >> 5;
    const int wn = wid >> 3, wc = wid & 7;
    const int n0 = blockIdx.x * 128;
    const uint32_t smb = smem_u32(sm);

    constexpr uint32_t SLOTK = (PLANES == 2) ? 36864u : 18432u;
    constexpr uint32_t WOFF  = (PLANES == 2) ? 12288u : 6144u;
    constexpr int WBLK = (PLANES == 2) ? 4096 : 2048;

    const __half *Wfam, *APh, *APm;
    int NB, CHW;
    if (MODE == 2)      { Wfam = g_WSK; NB = 128; APh = g_Z;   APm = g_Z;   CHW = 128; }
    else if (MODE == 3) { Wfam = g_W1b; NB = 16;  APh = g_ShP; APm = g_SmP; CHW = 256; }
    else                { Wfam = g_W2b; NB = 16;  APh = g_HhP; APm = g_HmP; CHW = 256; }

    uint32_t offA[4], offB[2];
    {
        int rA = wn * 64 + (lane & 15);
        int cA = (lane >> 4) * 16;
#pragma unroll
        for (int i = 0; i < 4; i++) offA[i] = (uint32_t)((rA + i * 16) * 48 + cA);
        int rB = wc * 32 + (lane >> 4) * 8 + (lane & 7);
        int cB = ((lane >> 3) & 1) * 16;
        offB[0] = (uint32_t)(rB * 48 + cB);
        offB[1] = (uint32_t)((rB + 16) * 48 + cB);
    }

    float acc[4][4][4];
#pragma unroll
    for (int i = 0; i < 4; i++)
#pragma unroll
        for (int j = 0; j < 4; j++)
#pragma unroll
            for (int k = 0; k < 4; k++) acc[i][j][k] = 0.f;

#define STAGE(cc, s) do {                                                         \
        if (PLANES == 2) {                                                        \
            int p = tid >> 8, r = (tid >> 1) & 127, hh = tid & 1;                 \
            int ch0 = (cc) * 16;                                                  \
            const __half* ap = p ? APm : APh;                                     \
            uint32_t d = smb + (s) * SLOTK + p * 6144u + r * 48u + hh * 16u;      \
            CPA16(d, ap + (size_t)(n0 + r) * CHW + ch0 + hh * 8, 16);             \
        } else if (tid < 256) {                                                   \
            int r = tid >> 1, hh = tid & 1;                                       \
            int ch0 = ((cc) & 7) * 16;                                            \
            const __half* ap = APh + (size_t)((cc) >> 3) * NTOT * 128;            \
            uint32_t d = smb + (s) * SLOTK + r * 48u + hh * 16u;                  \
            CPA16(d, ap + (size_t)(n0 + r) * CHW + ch0 + hh * 8, 16);             \
        }                                                                         \
        if (PLANES == 2) {                                                        \
            _Pragma("unroll")                                                     \
            for (int ii = 0; ii < 2; ii++) {                                      \
                int u = tid + ii * 512, p = (u >> 9) & 1, r = (u >> 1) & 255, hh = u & 1; \
                uint32_t d = smb + (s) * SLOTK + WOFF + p * 12288u + r * 48u + hh * 16u; \
                const __half* sp = Wfam + ((size_t)((r >> 7) * NB + (cc))) * WBLK \
                                   + p * 2048 + (r & 127) * 16 + hh * 8;          \
                CPA16(d, sp, 16);                                                 \
            }                                                                     \
        } else {                                                                  \
            int r = (tid >> 1) & 255, hh = tid & 1;                               \
            uint32_t d = smb + (s) * SLOTK + WOFF + r * 48u + hh * 16u;           \
            const __half* sp = Wfam + ((size_t)((r >> 7) * NB + (cc))) * WBLK     \
                               + (r & 127) * 16 + hh * 8;                         \
            CPA16(d, sp, 16);                                                     \
        }                                                                         \
    } while (0)

    STAGE(0, 0); CP_COMMIT();
    STAGE(1, 1); CP_COMMIT();
    STAGE(2, 2); CP_COMMIT();

#pragma unroll 1
    for (int c = 0; c < NCH; c++) {
        CP_WAIT2();
        __syncthreads();
        if (c + 3 < NCH) STAGE(c + 3, (c + 3) & 3);
        CP_COMMIT();

        const uint32_t base = smb + (uint32_t)(c & 3) * SLOTK;
        if (PLANES == 2) {
            uint32_t A1[4][4], A2[4][4], Bf[2][4];
#pragma unroll
            for (int i = 0; i < 4; i++) {
                LDM4(A1[i], base + offA[i]);
                LDM4(A2[i], base + 6144u + offA[i]);
            }
            LDM4(Bf[0], base + WOFF + offB[0]);
            LDM4(Bf[1], base + WOFF + offB[1]);
#pragma unroll
            for (int i = 0; i < 4; i++)
#pragma unroll
                for (int j = 0; j < 4; j++)
                    MMA(acc[i][j], A1[i], Bf[j >> 1][(j & 1) * 2], Bf[j >> 1][(j & 1) * 2 + 1]);
            LDM4(Bf[0], base + WOFF + 12288u + offB[0]);
            LDM4(Bf[1], base + WOFF + 12288u + offB[1]);
#pragma unroll
            for (int i = 0; i < 4; i++)
#pragma unroll
                for (int j = 0; j < 4; j++)
                    MMA(acc[i][j], A2[i], Bf[j >> 1][(j & 1) * 2], Bf[j >> 1][(j & 1) * 2 + 1]);
        } else {
            uint32_t Af[4][4], Bf[2][4];
#pragma unroll
            for (int i = 0; i < 4; i++) LDM4(Af[i], base + offA[i]);
            LDM4(Bf[0], base + WOFF + offB[0]);
            LDM4(Bf[1], base + WOFF + offB[1]);
#pragma unroll
            for (int i = 0; i < 4; i++)
#pragma unroll
                for (int j = 0; j < 4; j++)
                    MMA(acc[i][j], Af[i], Bf[j >> 1][(j & 1) * 2], Bf[j >> 1][(j & 1) * 2 + 1]);
        }
    }
#undef STAGE

#pragma unroll
    for (int j = 0; j < 4; j++) {
        const int col = wc * 32 + j * 8 + (lane & 3) * 2;
        float bv0, bv1;
        if (MODE == 2) { bv0 = g_Bsk[col]; bv1 = g_Bsk[col + 1]; }
        else           { bv0 = bA[col]; bv1 = bA[col + 1]; }
#pragma unroll
        for (int i = 0; i < 4; i++)
#pragma unroll
            for (int h = 0; h < 2; h++) {
                int na = n0 + wn * 64 + i * 16 + h * 8 + (lane >> 2);
                float v0 = acc[i][j][h * 2] + bv0;
                float v1 = acc[i][j][h * 2 + 1] + bv1;
                if (MODE == 2 || MODE == 3) {
                    float r0 = fmaxf(v0, 0.f), r1 = fmaxf(v1, 0.f);
                    __half h0, m0, h1, m1;
                    msplit(r0, h0, m0); msplit(r1, h1, m1);
                    __half2 hp; hp.x = h0; hp.y = h1;
                    __half2 mp; mp.x = m0; mp.y = m1;
                    __half* Oh = (MODE == 2) ? g_ShP : g_HhP;
                    __half* Om = (MODE == 2) ? g_SmP : g_HmP;
                    *reinterpret_cast<__half2*>(Oh + (size_t)na * 256 + col) = hp;
                    *reinterpret_cast<__half2*>(Om + (size_t)na * 256 + col) = mp;
                } else {
                    int b = na >> 14, t = na & (T_LEN - 1);
                    dout[((size_t)b * 256 + col) * T_LEN + t]     = v0;
                    dout[((size_t)b * 256 + col + 1) * T_LEN + t] = v1;
                }
            }
    }
}

// ---------------- launch ----------------
extern "C" void kernel_launch(void* const* d_in, const int* in_sizes, int n_in,
                              void* d_out, int out_size) {
    const float* wave  = (const float*)d_in[0];
    const float* W_in  = (const float*)d_in[1];
    const float* b_in  = (const float*)d_in[2];
    const float* Wf    = (const float*)d_in[3];
    const float* bf    = (const float*)d_in[4];
    const float* Wg    = (const float*)d_in[5];
    const float* bg    = (const float*)d_in[6];
    const float* Wres  = (const float*)d_in[7];
    const float* bres  = (const float*)d_in[8];
    const float* Wskip = (const float*)d_in[9];
    const float* bskip = (const float*)d_in[10];
    const float* W1    = (const float*)d_in[11];
    const float* b1    = (const float*)d_in[12];
    const float* W2    = (const float*)d_in[13];
    const float* b2    = (const float*)d_in[14];
    float* out = (float*)d_out;

    const int GS2 = 4 * 36864;   // 147456 (heads)
    const int GS1 = 4 * 18432;   //  73728 (skip)
    cudaFuncSetAttribute(fgres_kernel, cudaFuncAttributeMaxDynamicSharedMemorySize, FS_BYTES);
    cudaFuncSetAttribute(mma_kernel<2, 128, 1>, cudaFuncAttributeMaxDynamicSharedMemorySize, GS1);
    cudaFuncSetAttribute(mma_kernel<3, 16, 2>,  cudaFuncAttributeMaxDynamicSharedMemorySize, GS2);
    cudaFuncSetAttribute(mma_kernel<4, 16, 2>,  cudaFuncAttributeMaxDynamicSharedMemorySize, GS2);

    pack_fg<<<16 * 2 * 16 * 2048 / 256, 256>>>(Wf, Wg);
    pack_rs<<<16 * 8 * 2048 / 256, 256>>>(Wres);
    pack_sk<<<2 * 128 * 2048 / 256, 256>>>(Wskip, bskip);
    pack_h <<<2 * 16 * 2048 / 256, 256>>>(W1, W2);
    init_kernel<<<(size_t)NTOT * 128 / 256, 256>>>(wave, W_in, b_in);

    static const int dil[NBLK] = {1, 2, 4, 8, 16, 32, 64, 128,
                                  1, 2, 4, 8, 16, 32, 64, 128};

    for (int i = 0; i < NBLK; i++)
        fgres_kernel<<<NTOT / 128, 512, FS_BYTES>>>(i, dil[i], bf, bg, bres);

    mma_kernel<2, 128, 1><<<NTOT / 128, 512, GS1>>>(nullptr, nullptr);  // skip (single-plane)
    mma_kernel<3, 16, 2><<<NTOT / 128, 512, GS2>>>(b1, nullptr);        // head1
    mma_kernel<4, 16, 2><<<NTOT / 128, 512, GS2>>>(b2, out);            // head2
}

// round 14
// speedup vs baseline: 2.2170x; 1.0532x over previous
#include <cuda_runtime.h>
#include <cuda_fp16.h>
#include <cstdint>
#include <cstddef>

#define T_LEN 16384
#define NTOT  131072
#define NBLK  16

#define DELTA 0.015625f     // 2^-6
#define C1    0.984375f     // 1 - 2^-6

// ---------------- activations, time-major [n][ch] ----------------
__device__ __align__(16) __half g_Xh[2][(size_t)NTOT * 128];
__device__ __align__(16) __half g_Xm[2][(size_t)NTOT * 128];
__device__ __align__(16) __half g_Z [(size_t)NBLK * NTOT * 128];  // single fp16 (skip input)
__device__ __align__(16) __half g_ShP[(size_t)NTOT * 256];
__device__ __align__(16) __half g_SmP[(size_t)NTOT * 256];
__device__ __align__(16) __half g_HhP[(size_t)NTOT * 256];
__device__ __align__(16) __half g_HmP[(size_t)NTOT * 256];

// weight blocks. 2-plane: [plane2][row128][k16] (W1=C1*w, W2=(w-W1)*64). skip: single plane.
__device__ __align__(16) __half g_WFG[(size_t)NBLK * 2 * 16 * 4096];
__device__ __align__(16) __half g_WRS[(size_t)NBLK * 8 * 4096];
__device__ __align__(16) __half g_WSK[(size_t)2 * 128 * 2048];    // single fp16
__device__ __align__(16) __half g_W1b[(size_t)2 * 16 * 4096];
__device__ __align__(16) __half g_W2b[(size_t)2 * 16 * 4096];
__device__ float g_Bsk[256];

// ---------------- helpers ----------------
__device__ __forceinline__ uint32_t smem_u32(const void* p) {
    uint32_t a;
    asm("{ .reg .u64 t; cvta.to.shared.u64 t, %1; cvt.u32.u64 %0, t; }" : "=r"(a) : "l"(p));
    return a;
}
// activation split: h = fp16(v), m = fp16(2^-6*h + (v-h)); reconstruct v = C1*h + m
__device__ __forceinline__ void msplit(float v, __half& h, __half& m) {
    h = __float2half(v);
    float hf = __half2float(h);
    m = __float2half(DELTA * hf + (v - hf));
}
// weight split: W1 = fp16(C1*v), W2 = fp16((v-W1)*64); A1*W1 + A2*W2 ~= x*v
__device__ __forceinline__ void wsplit(float v, __half& w1, __half& w2) {
    w1 = __float2half(C1 * v);
    float w1f = __half2float(w1);
    w2 = __float2half((v - w1f) * 64.0f);
}
// z = tanh(f) * sigmoid(g), 2 exp + 1 fast-div (no IEEE division sequences)
__device__ __forceinline__ float gated_act(float f, float g) {
    float ef = __expf(-2.0f * fabsf(f));
    float eg = __expf(-g);
    float z = (1.0f - ef) * __fdividef(1.0f, (1.0f + ef) * (1.0f + eg));
    return copysignf(z, f);
}

// ---------------- packing ----------------
__global__ void pack_fg(const float* __restrict__ Wf, const float* __restrict__ Wg) {
    int idx = blockIdx.x * blockDim.x + threadIdx.x;
    int kin = idx & 15, row = (idx >> 4) & 127, c = (idx >> 11) & 15;
    int nt = (idx >> 15) & 1, l = idx >> 16;
    int m = nt * 128 + row, ch = m >> 1, isg = m & 1;
    int tap = (c < 8) ? 1 : 0;
    int cin = (c & 7) * 16 + kin;
    float v = 0.f;
    if (ch < 120 && cin < 120) {
        const float* s = isg ? Wg : Wf;
        v = s[(((size_t)l * 120 + ch) * 120 + cin) * 2 + tap];
    }
    __half h, mo; wsplit(v, h, mo);
    __half* blk = g_WFG + ((size_t)((l * 2 + nt) * 16 + c)) * 4096;
    blk[row * 16 + kin] = h;
    blk[2048 + row * 16 + kin] = mo;
}

__global__ void pack_rs(const float* __restrict__ Wres) {
    int idx = blockIdx.x * blockDim.x + threadIdx.x;
    int kin = idx & 15, row = (idx >> 4) & 127, c = (idx >> 11) & 7, l = idx >> 14;
    int cin = c * 16 + kin;
    float v = (row < 120 && cin < 120) ? Wres[((size_t)l * 120 + row) * 120 + cin] : 0.f;
    __half h, mo; wsplit(v, h, mo);
    __half* blk = g_WRS + ((size_t)(l * 8 + c)) * 4096;
    blk[row * 16 + kin] = h;
    blk[2048 + row * 16 + kin] = mo;
}

__global__ void pack_sk(const float* __restrict__ Wskip, const float* __restrict__ bskip) {
    int idx = blockIdx.x * blockDim.x + threadIdx.x;   // 2*128*2048
    int kin = idx & 15, row = (idx >> 4) & 127, c = (idx >> 11) & 127, nt = idx >> 18;
    int q = nt * 128 + row, lay = c >> 3, cin = (c & 7) * 16 + kin;
    float v = (q < 240 && cin < 120) ? Wskip[((size_t)lay * 240 + q) * 120 + cin] : 0.f;
    g_WSK[((size_t)(nt * 128 + c)) * 2048 + row * 16 + kin] = __float2half(v);
    if (idx < 256) {
        float s = 0.f;
        if (idx < 240) for (int j = 0; j < NBLK; j++) s += bskip[j * 240 + idx];
        g_Bsk[idx] = s;
    }
}

__global__ void pack_h(const float* __restrict__ W1, const float* __restrict__ W2) {
    int idx = blockIdx.x * blockDim.x + threadIdx.x;
    int kin = idx & 15, row = (idx >> 4) & 127, c = (idx >> 11) & 15, nt = idx >> 15;
    int q = nt * 128 + row, k = c * 16 + kin;
    float v1 = (k < 240) ? W1[(size_t)q * 240 + k] : 0.f;
    float v2 = W2[(size_t)q * 256 + k];
    __half h, mo;
    __half* b1 = g_W1b + ((size_t)(nt * 16 + c)) * 4096;
    __half* b2 = g_W2b + ((size_t)(nt * 16 + c)) * 4096;
    wsplit(v1, h, mo); b1[row * 16 + kin] = h; b1[2048 + row * 16 + kin] = mo;
    wsplit(v2, h, mo); b2[row * 16 + kin] = h; b2[2048 + row * 16 + kin] = mo;
}

__global__ void init_kernel(const float* __restrict__ wave,
                            const float* __restrict__ W_in,
                            const float* __restrict__ b_in) {
    int idx = blockIdx.x * blockDim.x + threadIdx.x;
    int n = idx >> 7, c = idx & 127;
    float x = (c < 120) ? (W_in[c] * wave[n] + b_in[c]) : 0.f;
    __half h, m; msplit(x, h, m);
    g_Xh[0][idx] = h; g_Xm[0][idx] = m;
}

// ---------------- asm macros ----------------
#define CPA16(dst, src, sz) \
    asm volatile("cp.async.cg.shared.global [%0], [%1], 16, %2;" \
                 :: "r"(dst), "l"(src), "r"(sz) : "memory")
#define CP_COMMIT() asm volatile("cp.async.commit_group;" ::: "memory")
#define CP_WAIT2()  asm volatile("cp.async.wait_group 2;" ::: "memory")

#define LDM4(rr, addr) \
    asm volatile("ldmatrix.sync.aligned.m8n8.x4.shared.b16 {%0,%1,%2,%3}, [%4];" \
                 : "=r"((rr)[0]), "=r"((rr)[1]), "=r"((rr)[2]), "=r"((rr)[3]) : "r"(addr))

#define MMA(cr, a, b0v, b1v) \
    asm volatile("mma.sync.aligned.m16n8k16.row.col.f32.f16.f16.f32 " \
                 "{%0,%1,%2,%3}, {%4,%5,%6,%7}, {%8,%9}, {%0,%1,%2,%3};" \
                 : "+f"((cr)[0]), "+f"((cr)[1]), "+f"((cr)[2]), "+f"((cr)[3]) \
                 : "r"((a)[0]), "r"((a)[1]), "r"((a)[2]), "r"((a)[3]), "r"(b0v), "r"(b1v))

// ---------------- fused FG + RES kernel: CTA 128(time) x 256(col), 512 thr, 4 stages ----------------
// Stage slot (36864B): Ah@0(6144) Am@6144 W1@12288(12288) W2@24576.
// z tile planes: zh@147456 (34816B), zm@+34816. pitch 272.
#define SLOT  36864u
#define ZOFF  147456u
#define ZPIT  272u
#define ZPL   34816u
#define FS_BYTES (147456 + 2 * 34816)   // 217088

__global__ void __launch_bounds__(512, 1) fgres_kernel(int layer, int dil,
        const float* __restrict__ bf, const float* __restrict__ bg,
        const float* __restrict__ bres) {
    extern __shared__ __align__(16) char sm[];
    const int tid = threadIdx.x, lane = tid & 31, wid = tid >> 5;
    const int wn = wid >> 3, wc = wid & 7;      // 2 time-groups(64) x 8 col-groups(32)
    const int n0 = blockIdx.x * 128;
    const uint32_t smb = smem_u32(sm);

    const __half* Xrh = g_Xh[layer & 1];
    const __half* Xrm = g_Xm[layer & 1];
    __half* Xwh = g_Xh[(layer + 1) & 1];
    __half* Xwm = g_Xm[(layer + 1) & 1];
    const __half* Wb  = g_WFG + (size_t)layer * 2 * 16 * 4096;
    const __half* WRb = g_WRS + (size_t)layer * 8 * 4096;

    uint32_t offA[4], offB[2], offRB;
    {
        int rA = wn * 64 + (lane & 15);
        int cA = (lane >> 4) * 16;
#pragma unroll
        for (int i = 0; i < 4; i++) offA[i] = (uint32_t)((rA + i * 16) * 48 + cA);
        int rB = wc * 32 + (lane >> 4) * 8 + (lane & 7);
        int cB = ((lane >> 3) & 1) * 16;
        offB[0] = (uint32_t)(rB * 48 + cB);
        offB[1] = (uint32_t)((rB + 16) * 48 + cB);
        int rR = wc * 16 + (lane >> 4) * 8 + (lane & 7);
        offRB = (uint32_t)(rR * 48 + cB);
    }

    float acc[4][4][4];
#pragma unroll
    for (int i = 0; i < 4; i++)
#pragma unroll
        for (int j = 0; j < 4; j++)
#pragma unroll
            for (int k = 0; k < 4; k++) acc[i][j][k] = 0.f;

#define FSTAGE(cc, s) do {                                                        \
        {   /* A: 2 planes x 128 rows x 32B = 8KB, 1 op/thread */                 \
            int p = tid >> 8, r = (tid >> 1) & 127, hh = tid & 1;                 \
            int na = n0 + r, nn = na, sz = 16, ch0;                               \
            if ((cc) < 8) ch0 = (cc) * 16;                                        \
            else {                                                                \
                ch0 = ((cc) - 8) * 16;                                            \
                int t = na & (T_LEN - 1);                                         \
                if (t >= dil) nn = na - dil; else sz = 0;                         \
            }                                                                     \
            uint32_t d = smb + (s) * SLOT + p * 6144u + r * 48u + hh * 16u;       \
            const __half* gp = (p ? Xrm : Xrh) + (size_t)nn * 128 + ch0 + hh * 8; \
            CPA16(d, gp, sz);                                                     \
        }                                                                         \
        _Pragma("unroll")                                                         \
        for (int ii = 0; ii < 2; ii++) {   /* W: 2 planes x 256 rows x 32B = 16KB */ \
            int u = tid + ii * 512, p = (u >> 9) & 1, r = (u >> 1) & 255, hh = u & 1; \
            uint32_t d = smb + (s) * SLOT + 12288u + p * 12288u + r * 48u + hh * 16u; \
            const __half* sp = Wb + ((size_t)((r >> 7) * 16 + (cc))) * 4096       \
                               + p * 2048 + (r & 127) * 16 + hh * 8;              \
            CPA16(d, sp, 16);                                                     \
        }                                                                         \
    } while (0)

    FSTAGE(0, 0); CP_COMMIT();
    FSTAGE(1, 1); CP_COMMIT();
    FSTAGE(2, 2); CP_COMMIT();

#pragma unroll 1
    for (int c = 0; c < 16; c++) {
        CP_WAIT2();
        __syncthreads();
        if (c + 3 < 16) FSTAGE(c + 3, (c + 3) & 3);
        CP_COMMIT();

        const uint32_t base = smb + (uint32_t)(c & 3) * SLOT;
        uint32_t A1[4][4], A2[4][4], Bf[2][4];
#pragma unroll
        for (int i = 0; i < 4; i++) {
            LDM4(A1[i], base + offA[i]);
            LDM4(A2[i], base + 6144u + offA[i]);
        }
        LDM4(Bf[0], base + 12288u + offB[0]);
        LDM4(Bf[1], base + 12288u + offB[1]);
#pragma unroll
        for (int i = 0; i < 4; i++)
#pragma unroll
            for (int j = 0; j < 4; j++)
                MMA(acc[i][j], A1[i], Bf[j >> 1][(j & 1) * 2], Bf[j >> 1][(j & 1) * 2 + 1]);
        LDM4(Bf[0], base + 24576u + offB[0]);
        LDM4(Bf[1], base + 24576u + offB[1]);
#pragma unroll
        for (int i = 0; i < 4; i++)
#pragma unroll
            for (int j = 0; j < 4; j++)
                MMA(acc[i][j], A2[i], Bf[j >> 1][(j & 1) * 2], Bf[j >> 1][(j & 1) * 2 + 1]);
    }
#undef FSTAGE

    // RES W prefetch (slots 0..2 are no longer being read; slot 3 handled in loop).
#define RSTAGE(rc, s) do {                                                        \
        int p = tid >> 8, r = (tid >> 1) & 127, hh = tid & 1;                     \
        uint32_t d = smb + (s) * SLOT + p * 6144u + r * 48u + hh * 16u;           \
        const __half* sp = WRb + (size_t)(rc) * 4096 + p * 2048 + r * 16 + hh * 8; \
        CPA16(d, sp, 16);                                                         \
    } while (0)

    __syncthreads();   // all FG reads of all slots done before RES W overwrites
    RSTAGE(0, 0); CP_COMMIT();
    RSTAGE(1, 1); CP_COMMIT();
    RSTAGE(2, 2); CP_COMMIT();

    // ---- epilogue 1: z = tanh(f)*sigmoid(g); 2-plane to SMEM, single-plane to gmem ----
#pragma unroll
    for (int j = 0; j < 4; j++) {
        int c0 = wc * 32 + j * 8 + (lane & 3) * 2;
        int ch = c0 >> 1;
        float bfv = 0.f, bgv = 0.f;
        if (ch < 120) { bfv = bf[layer * 120 + ch]; bgv = bg[layer * 120 + ch]; }
#pragma unroll
        for (int i = 0; i < 4; i++)
#pragma unroll
            for (int h = 0; h < 2; h++) {
                int row = wn * 64 + i * 16 + h * 8 + (lane >> 2);
                float z = gated_act(acc[i][j][h * 2] + bfv, acc[i][j][h * 2 + 1] + bgv);
                __half zh, zm; msplit(z, zh, zm);
                *reinterpret_cast<__half*>(sm + ZOFF + row * ZPIT + ch * 2) = zh;
                *reinterpret_cast<__half*>(sm + ZOFF + ZPL + row * ZPIT + ch * 2) = zm;
                g_Z[(size_t)layer * NTOT * 128 + (size_t)(n0 + row) * 128 + ch] =
                    __float2half(z);
            }
    }

    // ---- RES GEMM: res[128t x 128ch] = z @ Wres^T (z from SMEM planes) ----
    float racc[4][2][4];
#pragma unroll
    for (int i = 0; i < 4; i++)
#pragma unroll
        for (int j = 0; j < 2; j++)
#pragma unroll
            for (int k = 0; k < 4; k++) racc[i][j][k] = 0.f;

#pragma unroll 1
    for (int rc = 0; rc < 8; rc++) {
        CP_WAIT2();
        __syncthreads();
        if (rc + 3 < 8) RSTAGE(rc + 3, (rc + 3) & 3);
        CP_COMMIT();

        const uint32_t base = smb + (uint32_t)(rc & 3) * SLOT;
        uint32_t Z1[4][4], Z2[4][4], RB[4];
        uint32_t zk = (uint32_t)(rc * 32) + (lane >> 4) * 16;
#pragma unroll
        for (int i = 0; i < 4; i++) {
            uint32_t zr = smb + ZOFF + (wn * 64 + i * 16 + (lane & 15)) * ZPIT + zk;
            LDM4(Z1[i], zr);
            LDM4(Z2[i], zr + ZPL);
        }
        LDM4(RB, base + offRB);
#pragma unroll
        for (int i = 0; i < 4; i++)
#pragma unroll
            for (int j = 0; j < 2; j++)
                MMA(racc[i][j], Z1[i], RB[j * 2], RB[j * 2 + 1]);
        LDM4(RB, base + 6144u + offRB);
#pragma unroll
        for (int i = 0; i < 4; i++)
#pragma unroll
            for (int j = 0; j < 2; j++)
                MMA(racc[i][j], Z2[i], RB[j * 2], RB[j * 2 + 1]);
    }
#undef RSTAGE

    // ---- epilogue 2: X_next = (C1*Xh + Xm) + res + bres, split-stored ----
#pragma unroll
    for (int j = 0; j < 2; j++) {
        int col = wc * 16 + j * 8 + (lane & 3) * 2;
        if (col < 120) {
            float bv0 = bres[layer * 120 + col];
            float bv1 = bres[layer * 120 + col + 1];
#pragma unroll
            for (int i = 0; i < 4; i++)
#pragma unroll
                for (int h = 0; h < 2; h++) {
                    int row = n0 + wn * 64 + i * 16 + h * 8 + (lane >> 2);
                    size_t off = (size_t)row * 128 + col;
                    __half2 xh = *reinterpret_cast<const __half2*>(Xrh + off);
                    __half2 xm = *reinterpret_cast<const __half2*>(Xrm + off);
                    float x0 = C1 * __half2float(xh.x) + __half2float(xm.x)
                             + racc[i][j][h * 2] + bv0;
                    float x1 = C1 * __half2float(xh.y) + __half2float(xm.y)
                             + racc[i][j][h * 2 + 1] + bv1;
                    __half h0, m0, h1, m1;
                    msplit(x0, h0, m0); msplit(x1, h1, m1);
                    __half2 hp; hp.x = h0; hp.y = h1;
                    __half2 mp; mp.x = m0; mp.y = m1;
                    *reinterpret_cast<__half2*>(Xwh + off) = hp;
                    *reinterpret_cast<__half2*>(Xwm + off) = mp;
                }
        }
    }
}

// ---------------- generic GEMM: CTA 128 x 256, 512 thr, 4 stages ----------------
// MODE 2 = SKIP (PLANES=1, single fp16 z & w), MODE 3 = H1, MODE 4 = H2 (PLANES=2).
template<int MODE, int NCH, int PLANES>
__global__ void __launch_bounds__(512, 1) mma_kernel(const float* __restrict__ bA,
                                                     float* __restrict__ dout) {
    extern __shared__ __align__(16) char sm[];
    const int tid = threadIdx.x, lane = tid & 31, wid = tid >> 5;
    const int wn = wid >> 3, wc = wid & 7;
    const int n0 = blockIdx.x * 128;
    const uint32_t smb = smem_u32(sm);

    constexpr uint32_t SLOTK = (PLANES == 2) ? 36864u : 18432u;
    constexpr uint32_t WOFF  = (PLANES == 2) ? 12288u : 6144u;
    constexpr int WBLK = (PLANES == 2) ? 4096 : 2048;

    const __half *Wfam, *APh, *APm;
    int NB, CHW;
    if (MODE == 2)      { Wfam = g_WSK; NB = 128; APh = g_Z;   APm = g_Z;   CHW = 128; }
    else if (MODE == 3) { Wfam = g_W1b; NB = 16;  APh = g_ShP; APm = g_SmP; CHW = 256; }
    else                { Wfam = g_W2b; NB = 16;  APh = g_HhP; APm = g_HmP; CHW = 256; }

    uint32_t offA[4], offB[2];
    {
        int rA = wn * 64 + (lane & 15);
        int cA = (lane >> 4) * 16;
#pragma unroll
        for (int i = 0; i < 4; i++) offA[i] = (uint32_t)((rA + i * 16) * 48 + cA);
        int rB = wc * 32 + (lane >> 4) * 8 + (lane & 7);
        int cB = ((lane >> 3) & 1) * 16;
        offB[0] = (uint32_t)(rB * 48 + cB);
        offB[1] = (uint32_t)((rB + 16) * 48 + cB);
    }

    float acc[4][4][4];
#pragma unroll
    for (int i = 0; i < 4; i++)
#pragma unroll
        for (int j = 0; j < 4; j++)
#pragma unroll
            for (int k = 0; k < 4; k++) acc[i][j][k] = 0.f;

#define STAGE(cc, s) do {                                                         \
        if (PLANES == 2) {                                                        \
            int p = tid >> 8, r = (tid >> 1) & 127, hh = tid & 1;                 \
            int ch0 = (cc) * 16;                                                  \
            const __half* ap = p ? APm : APh;                                     \
            uint32_t d = smb + (s) * SLOTK + p * 6144u + r * 48u + hh * 16u;      \
            CPA16(d, ap + (size_t)(n0 + r) * CHW + ch0 + hh * 8, 16);             \
        } else if (tid < 256) {                                                   \
            int r = tid >> 1, hh = tid & 1;                                       \
            int ch0 = ((cc) & 7) * 16;                                            \
            const __half* ap = APh + (size_t)((cc) >> 3) * NTOT * 128;            \
            uint32_t d = smb + (s) * SLOTK + r * 48u + hh * 16u;                  \
            CPA16(d, ap + (size_t)(n0 + r) * CHW + ch0 + hh * 8, 16);             \
        }                                                                         \
        if (PLANES == 2) {                                                        \
            _Pragma("unroll")                                                     \
            for (int ii = 0; ii < 2; ii++) {                                      \
                int u = tid + ii * 512, p = (u >> 9) & 1, r = (u >> 1) & 255, hh = u & 1; \
                uint32_t d = smb + (s) * SLOTK + WOFF + p * 12288u + r * 48u + hh * 16u; \
                const __half* sp = Wfam + ((size_t)((r >> 7) * NB + (cc))) * WBLK \
                                   + p * 2048 + (r & 127) * 16 + hh * 8;          \
                CPA16(d, sp, 16);                                                 \
            }                                                                     \
        } else {                                                                  \
            int r = (tid >> 1) & 255, hh = tid & 1;                               \
            uint32_t d = smb + (s) * SLOTK + WOFF + r * 48u + hh * 16u;           \
            const __half* sp = Wfam + ((size_t)((r >> 7) * NB + (cc))) * WBLK     \
                               + (r & 127) * 16 + hh * 8;                         \
            CPA16(d, sp, 16);                                                     \
        }                                                                         \
    } while (0)

    STAGE(0, 0); CP_COMMIT();
    STAGE(1, 1); CP_COMMIT();
    STAGE(2, 2); CP_COMMIT();

#pragma unroll 1
    for (int c = 0; c < NCH; c++) {
        CP_WAIT2();
        __syncthreads();
        if (c + 3 < NCH) STAGE(c + 3, (c + 3) & 3);
        CP_COMMIT();

        const uint32_t base = smb + (uint32_t)(c & 3) * SLOTK;
        if (PLANES == 2) {
            uint32_t A1[4][4], A2[4][4], Bf[2][4];
#pragma unroll
            for (int i = 0; i < 4; i++) {
                LDM4(A1[i], base + offA[i]);
                LDM4(A2[i], base + 6144u + offA[i]);
            }
            LDM4(Bf[0], base + WOFF + offB[0]);
            LDM4(Bf[1], base + WOFF + offB[1]);
#pragma unroll
            for (int i = 0; i < 4; i++)
#pragma unroll
                for (int j = 0; j < 4; j++)
                    MMA(acc[i][j], A1[i], Bf[j >> 1][(j & 1) * 2], Bf[j >> 1][(j & 1) * 2 + 1]);
            LDM4(Bf[0], base + WOFF + 12288u + offB[0]);
            LDM4(Bf[1], base + WOFF + 12288u + offB[1]);
#pragma unroll
            for (int i = 0; i < 4; i++)
#pragma unroll
                for (int j = 0; j < 4; j++)
                    MMA(acc[i][j], A2[i], Bf[j >> 1][(j & 1) * 2], Bf[j >> 1][(j & 1) * 2 + 1]);
        } else {
            uint32_t Af[4][4], Bf[2][4];
#pragma unroll
            for (int i = 0; i < 4; i++) LDM4(Af[i], base + offA[i]);
            LDM4(Bf[0], base + WOFF + offB[0]);
            LDM4(Bf[1], base + WOFF + offB[1]);
#pragma unroll
            for (int i = 0; i < 4; i++)
#pragma unroll
                for (int j = 0; j < 4; j++)
                    MMA(acc[i][j], Af[i], Bf[j >> 1][(j & 1) * 2], Bf[j >> 1][(j & 1) * 2 + 1]);
        }
    }
#undef STAGE

#pragma unroll
    for (int j = 0; j < 4; j++) {
        const int col = wc * 32 + j * 8 + (lane & 3) * 2;
        float bv0, bv1;
        if (MODE == 2) { bv0 = g_Bsk[col]; bv1 = g_Bsk[col + 1]; }
        else           { bv0 = bA[col]; bv1 = bA[col + 1]; }
#pragma unroll
        for (int i = 0; i < 4; i++)
#pragma unroll
            for (int h = 0; h < 2; h++) {
                int na = n0 + wn * 64 + i * 16 + h * 8 + (lane >> 2);
                float v0 = acc[i][j][h * 2] + bv0;
                float v1 = acc[i][j][h * 2 + 1] + bv1;
                if (MODE == 2 || MODE == 3) {
                    float r0 = fmaxf(v0, 0.f), r1 = fmaxf(v1, 0.f);
                    __half h0, m0, h1, m1;
                    msplit(r0, h0, m0); msplit(r1, h1, m1);
                    __half2 hp; hp.x = h0; hp.y = h1;
                    __half2 mp; mp.x = m0; mp.y = m1;
                    __half* Oh = (MODE == 2) ? g_ShP : g_HhP;
                    __half* Om = (MODE == 2) ? g_SmP : g_HmP;
                    *reinterpret_cast<__half2*>(Oh + (size_t)na * 256 + col) = hp;
                    *reinterpret_cast<__half2*>(Om + (size_t)na * 256 + col) = mp;
                } else {
                    int b = na >> 14, t = na & (T_LEN - 1);
                    dout[((size_t)b * 256 + col) * T_LEN + t]     = v0;
                    dout[((size_t)b * 256 + col + 1) * T_LEN + t] = v1;
                }
            }
    }
}

// ---------------- launch ----------------
extern "C" void kernel_launch(void* const* d_in, const int* in_sizes, int n_in,
                              void* d_out, int out_size) {
    const float* wave  = (const float*)d_in[0];
    const float* W_in  = (const float*)d_in[1];
    const float* b_in  = (const float*)d_in[2];
    const float* Wf    = (const float*)d_in[3];
    const float* bf    = (const float*)d_in[4];
    const float* Wg    = (const float*)d_in[5];
    const float* bg    = (const float*)d_in[6];
    const float* Wres  = (const float*)d_in[7];
    const float* bres  = (const float*)d_in[8];
    const float* Wskip = (const float*)d_in[9];
    const float* bskip = (const float*)d_in[10];
    const float* W1    = (const float*)d_in[11];
    const float* b1    = (const float*)d_in[12];
    const float* W2    = (const float*)d_in[13];
    const float* b2    = (const float*)d_in[14];
    float* out = (float*)d_out;

    const int GS2 = 4 * 36864;   // 147456 (heads)
    const int GS1 = 4 * 18432;   //  73728 (skip)
    cudaFuncSetAttribute(fgres_kernel, cudaFuncAttributeMaxDynamicSharedMemorySize, FS_BYTES);
    cudaFuncSetAttribute(mma_kernel<2, 128, 1>, cudaFuncAttributeMaxDynamicSharedMemorySize, GS1);
    cudaFuncSetAttribute(mma_kernel<3, 16, 2>,  cudaFuncAttributeMaxDynamicSharedMemorySize, GS2);
    cudaFuncSetAttribute(mma_kernel<4, 16, 2>,  cudaFuncAttributeMaxDynamicSharedMemorySize, GS2);

    pack_fg<<<16 * 2 * 16 * 2048 / 256, 256>>>(Wf, Wg);
    pack_rs<<<16 * 8 * 2048 / 256, 256>>>(Wres);
    pack_sk<<<2 * 128 * 2048 / 256, 256>>>(Wskip, bskip);
    pack_h <<<2 * 16 * 2048 / 256, 256>>>(W1, W2);
    init_kernel<<<(size_t)NTOT * 128 / 256, 256>>>(wave, W_in, b_in);

    static const int dil[NBLK] = {1, 2, 4, 8, 16, 32, 64, 128,
                                  1, 2, 4, 8, 16, 32, 64, 128};

    for (int i = 0; i < NBLK; i++)
        fgres_kernel<<<NTOT / 128, 512, FS_BYTES>>>(i, dil[i], bf, bg, bres);

    mma_kernel<2, 128, 1><<<NTOT / 128, 512, GS1>>>(nullptr, nullptr);  // skip (single-plane)
    mma_kernel<3, 16, 2><<<NTOT / 128, 512, GS2>>>(b1, nullptr);        // head1
    mma_kernel<4, 16, 2><<<NTOT / 128, 512, GS2>>>(b2, out);            // head2
}

// round 15
// speedup vs baseline: 2.2910x; 1.0334x over previous
#include <cuda_runtime.h>
#include <cuda_fp16.h>
#include <cstdint>
#include <cstddef>

#define T_LEN 16384
#define NTOT  131072
#define NBLK  16

#define DELTA 0.015625f     // 2^-6
#define C1    0.984375f     // 1 - 2^-6

// ---------------- activations, time-major [n][ch] ----------------
__device__ __align__(16) __half g_Xh[2][(size_t)NTOT * 128];
__device__ __align__(16) __half g_Xm[2][(size_t)NTOT * 128];
__device__ __align__(16) __half g_Z [(size_t)NBLK * NTOT * 128];  // single fp16 (skip input)
__device__ __align__(16) __half g_ShP[(size_t)NTOT * 256];
__device__ __align__(16) __half g_SmP[(size_t)NTOT * 256];
__device__ __align__(16) __half g_HhP[(size_t)NTOT * 256];
__device__ __align__(16) __half g_HmP[(size_t)NTOT * 256];

// weight blocks. 2-plane: [plane2][row128][k16] (W1=C1*w, W2=(w-W1)*64). skip: single plane.
__device__ __align__(16) __half g_WFG[(size_t)NBLK * 2 * 16 * 4096];
__device__ __align__(16) __half g_WRS[(size_t)NBLK * 8 * 4096];
__device__ __align__(16) __half g_WSK[(size_t)2 * 128 * 2048];    // single fp16
__device__ __align__(16) __half g_W1b[(size_t)2 * 16 * 4096];
__device__ __align__(16) __half g_W2b[(size_t)2 * 16 * 4096];
__device__ float g_Bsk[256];

// ---------------- helpers ----------------
__device__ __forceinline__ uint32_t smem_u32(const void* p) {
    uint32_t a;
    asm("{ .reg .u64 t; cvta.to.shared.u64 t, %1; cvt.u32.u64 %0, t; }" : "=r"(a) : "l"(p));
    return a;
}
// activation split: h = fp16(v), m = fp16(2^-6*h + (v-h)); reconstruct v = C1*h + m
__device__ __forceinline__ void msplit(float v, __half& h, __half& m) {
    h = __float2half(v);
    float hf = __half2float(h);
    m = __float2half(DELTA * hf + (v - hf));
}
// weight split: W1 = fp16(C1*v), W2 = fp16((v-W1)*64); A1*W1 + A2*W2 ~= x*v
__device__ __forceinline__ void wsplit(float v, __half& w1, __half& w2) {
    w1 = __float2half(C1 * v);
    float w1f = __half2float(w1);
    w2 = __float2half((v - w1f) * 64.0f);
}
// z = tanh(f) * sigmoid(g), 2 exp + 1 fast-div
__device__ __forceinline__ float gated_act(float f, float g) {
    float ef = __expf(-2.0f * fabsf(f));
    float eg = __expf(-g);
    float z = (1.0f - ef) * __fdividef(1.0f, (1.0f + ef) * (1.0f + eg));
    return copysignf(z, f);
}

// ---------------- packing ----------------
__global__ void pack_fg(const float* __restrict__ Wf, const float* __restrict__ Wg) {
    int idx = blockIdx.x * blockDim.x + threadIdx.x;
    int kin = idx & 15, row = (idx >> 4) & 127, c = (idx >> 11) & 15;
    int nt = (idx >> 15) & 1, l = idx >> 16;
    int m = nt * 128 + row, ch = m >> 1, isg = m & 1;
    int tap = (c < 8) ? 1 : 0;
    int cin = (c & 7) * 16 + kin;
    float v = 0.f;
    if (ch < 120 && cin < 120) {
        const float* s = isg ? Wg : Wf;
        v = s[(((size_t)l * 120 + ch) * 120 + cin) * 2 + tap];
    }
    __half h, mo; wsplit(v, h, mo);
    __half* blk = g_WFG + ((size_t)((l * 2 + nt) * 16 + c)) * 4096;
    blk[row * 16 + kin] = h;
    blk[2048 + row * 16 + kin] = mo;
}

__global__ void pack_rs(const float* __restrict__ Wres) {
    int idx = blockIdx.x * blockDim.x + threadIdx.x;
    int kin = idx & 15, row = (idx >> 4) & 127, c = (idx >> 11) & 7, l = idx >> 14;
    int cin = c * 16 + kin;
    float v = (row < 120 && cin < 120) ? Wres[((size_t)l * 120 + row) * 120 + cin] : 0.f;
    __half h, mo; wsplit(v, h, mo);
    __half* blk = g_WRS + ((size_t)(l * 8 + c)) * 4096;
    blk[row * 16 + kin] = h;
    blk[2048 + row * 16 + kin] = mo;
}

__global__ void pack_sk(const float* __restrict__ Wskip, const float* __restrict__ bskip) {
    int idx = blockIdx.x * blockDim.x + threadIdx.x;   // 2*128*2048
    int kin = idx & 15, row = (idx >> 4) & 127, c = (idx >> 11) & 127, nt = idx >> 18;
    int q = nt * 128 + row, lay = c >> 3, cin = (c & 7) * 16 + kin;
    float v = (q < 240 && cin < 120) ? Wskip[((size_t)lay * 240 + q) * 120 + cin] : 0.f;
    g_WSK[((size_t)(nt * 128 + c)) * 2048 + row * 16 + kin] = __float2half(v);
    if (idx < 256) {
        float s = 0.f;
        if (idx < 240) for (int j = 0; j < NBLK; j++) s += bskip[j * 240 + idx];
        g_Bsk[idx] = s;
    }
}

__global__ void pack_h(const float* __restrict__ W1, const float* __restrict__ W2) {
    int idx = blockIdx.x * blockDim.x + threadIdx.x;
    int kin = idx & 15, row = (idx >> 4) & 127, c = (idx >> 11) & 15, nt = idx >> 15;
    int q = nt * 128 + row, k = c * 16 + kin;
    float v1 = (k < 240) ? W1[(size_t)q * 240 + k] : 0.f;
    float v2 = W2[(size_t)q * 256 + k];
    __half h, mo;
    __half* b1 = g_W1b + ((size_t)(nt * 16 + c)) * 4096;
    __half* b2 = g_W2b + ((size_t)(nt * 16 + c)) * 4096;
    wsplit(v1, h, mo); b1[row * 16 + kin] = h; b1[2048 + row * 16 + kin] = mo;
    wsplit(v2, h, mo); b2[row * 16 + kin] = h; b2[2048 + row * 16 + kin] = mo;
}

__global__ void init_kernel(const float* __restrict__ wave,
                            const float* __restrict__ W_in,
                            const float* __restrict__ b_in) {
    int idx = blockIdx.x * blockDim.x + threadIdx.x;
    int n = idx >> 7, c = idx & 127;
    float x = (c < 120) ? (W_in[c] * wave[n] + b_in[c]) : 0.f;
    __half h, m; msplit(x, h, m);
    g_Xh[0][idx] = h; g_Xm[0][idx] = m;
}

// ---------------- asm macros ----------------
#define CPA16(dst, src, sz) \
    asm volatile("cp.async.cg.shared.global [%0], [%1], 16, %2;" \
                 :: "r"(dst), "l"(src), "r"(sz) : "memory")
#define CP_COMMIT() asm volatile("cp.async.commit_group;" ::: "memory")
#define CP_WAIT2()  asm volatile("cp.async.wait_group 2;" ::: "memory")

#define LDM4(rr, addr) \
    asm volatile("ldmatrix.sync.aligned.m8n8.x4.shared.b16 {%0,%1,%2,%3}, [%4];" \
                 : "=r"((rr)[0]), "=r"((rr)[1]), "=r"((rr)[2]), "=r"((rr)[3]) : "r"(addr))

#define MMA(cr, a, b0v, b1v) \
    asm volatile("mma.sync.aligned.m16n8k16.row.col.f32.f16.f16.f32 " \
                 "{%0,%1,%2,%3}, {%4,%5,%6,%7}, {%8,%9}, {%0,%1,%2,%3};" \
                 : "+f"((cr)[0]), "+f"((cr)[1]), "+f"((cr)[2]), "+f"((cr)[3]) \
                 : "r"((a)[0]), "r"((a)[1]), "r"((a)[2]), "r"((a)[3]), "r"(b0v), "r"(b1v))

// ---------------- fused FG + RES kernel: CTA 128(time) x 256(col), 512 thr, 4 stages ----------------
// Stage slot (36864B): Ah@0(6144) Am@6144 W1@12288(12288) W2@24576.
// z tile planes: zh@147456 (34816B), zm@+34816. pitch 272.
#define SLOT  36864u
#define ZOFF  147456u
#define ZPIT  272u
#define ZPL   34816u
#define FS_BYTES (147456 + 2 * 34816)   // 217088

__global__ void __launch_bounds__(512, 1) fgres_kernel(int layer, int dil,
        const float* __restrict__ bf, const float* __restrict__ bg,
        const float* __restrict__ bres) {
    extern __shared__ __align__(16) char sm[];
    const int tid = threadIdx.x, lane = tid & 31, wid = tid >> 5;
    const int wn = wid >> 3, wc = wid & 7;      // 2 time-groups(64) x 8 col-groups(32)
    const int n0 = blockIdx.x * 128;
    const uint32_t smb = smem_u32(sm);

    const __half* Xrh = g_Xh[layer & 1];
    const __half* Xrm = g_Xm[layer & 1];
    __half* Xwh = g_Xh[(layer + 1) & 1];
    __half* Xwm = g_Xm[(layer + 1) & 1];
    const __half* Wb  = g_WFG + (size_t)layer * 2 * 16 * 4096;
    const __half* WRb = g_WRS + (size_t)layer * 8 * 4096;

    uint32_t offA[4], offB[2], offRB;
    {
        int rA = wn * 64 + (lane & 15);
        int cA = (lane >> 4) * 16;
#pragma unroll
        for (int i = 0; i < 4; i++) offA[i] = (uint32_t)((rA + i * 16) * 48 + cA);
        int rB = wc * 32 + (lane >> 4) * 8 + (lane & 7);
        int cB = ((lane >> 3) & 1) * 16;
        offB[0] = (uint32_t)(rB * 48 + cB);
        offB[1] = (uint32_t)((rB + 16) * 48 + cB);
        int rR = wc * 16 + (lane >> 4) * 8 + (lane & 7);
        offRB = (uint32_t)(rR * 48 + cB);
    }

    float acc[4][4][4];
#pragma unroll
    for (int i = 0; i < 4; i++)
#pragma unroll
        for (int j = 0; j < 4; j++)
#pragma unroll
            for (int k = 0; k < 4; k++) acc[i][j][k] = 0.f;

#define FSTAGE(cc, s) do {                                                        \
        {   /* A: 2 planes x 128 rows x 32B = 8KB, 1 op/thread */                 \
            int p = tid >> 8, r = (tid >> 1) & 127, hh = tid & 1;                 \
            int na = n0 + r, nn = na, sz = 16, ch0;                               \
            if ((cc) < 8) ch0 = (cc) * 16;                                        \
            else {                                                                \
                ch0 = ((cc) - 8) * 16;                                            \
                int t = na & (T_LEN - 1);                                         \
                if (t >= dil) nn = na - dil; else sz = 0;                         \
            }                                                                     \
            uint32_t d = smb + (s) * SLOT + p * 6144u + r * 48u + hh * 16u;       \
            const __half* gp = (p ? Xrm : Xrh) + (size_t)nn * 128 + ch0 + hh * 8; \
            CPA16(d, gp, sz);                                                     \
        }                                                                         \
        _Pragma("unroll")                                                         \
        for (int ii = 0; ii < 2; ii++) {   /* W: 2 planes x 256 rows x 32B = 16KB */ \
            int u = tid + ii * 512, p = (u >> 9) & 1, r = (u >> 1) & 255, hh = u & 1; \
            uint32_t d = smb + (s) * SLOT + 12288u + p * 12288u + r * 48u + hh * 16u; \
            const __half* sp = Wb + ((size_t)((r >> 7) * 16 + (cc))) * 4096       \
                               + p * 2048 + (r & 127) * 16 + hh * 8;              \
            CPA16(d, sp, 16);                                                     \
        }                                                                         \
    } while (0)

    FSTAGE(0, 0); CP_COMMIT();
    FSTAGE(1, 1); CP_COMMIT();
    FSTAGE(2, 2); CP_COMMIT();

#pragma unroll 1
    for (int c = 0; c < 16; c++) {
        CP_WAIT2();
        __syncthreads();
        if (c + 3 < 16) FSTAGE(c + 3, (c + 3) & 3);
        CP_COMMIT();

        const uint32_t base = smb + (uint32_t)(c & 3) * SLOT;
        uint32_t A1[4][4], A2[4][4], Bf[2][4];
#pragma unroll
        for (int i = 0; i < 4; i++) {
            LDM4(A1[i], base + offA[i]);
            LDM4(A2[i], base + 6144u + offA[i]);
        }
        LDM4(Bf[0], base + 12288u + offB[0]);
        LDM4(Bf[1], base + 12288u + offB[1]);
#pragma unroll
        for (int i = 0; i < 4; i++)
#pragma unroll
            for (int j = 0; j < 4; j++)
                MMA(acc[i][j], A1[i], Bf[j >> 1][(j & 1) * 2], Bf[j >> 1][(j & 1) * 2 + 1]);
        LDM4(Bf[0], base + 24576u + offB[0]);
        LDM4(Bf[1], base + 24576u + offB[1]);
#pragma unroll
        for (int i = 0; i < 4; i++)
#pragma unroll
            for (int j = 0; j < 4; j++)
                MMA(acc[i][j], A2[i], Bf[j >> 1][(j & 1) * 2], Bf[j >> 1][(j & 1) * 2 + 1]);
    }
#undef FSTAGE

    // RES W prefetch: 2 chunks per slot (chunk sub at +sub*12288; planes at +0 / +6144)
#define RSTAGE2(rc2, s) do {                                                      \
        _Pragma("unroll")                                                         \
        for (int sub = 0; sub < 2; sub++) {                                       \
            int rc = 2 * (rc2) + sub;                                             \
            int p = tid >> 8, r = (tid >> 1) & 127, hh = tid & 1;                 \
            uint32_t d = smb + (s) * SLOT + sub * 12288u + p * 6144u + r * 48u + hh * 16u; \
            const __half* sp = WRb + (size_t)rc * 4096 + p * 2048 + r * 16 + hh * 8; \
            CPA16(d, sp, 16);                                                     \
        }                                                                         \
    } while (0)

    __syncthreads();   // all FG reads of all slots done before RES W overwrites
    RSTAGE2(0, 0); CP_COMMIT();
    RSTAGE2(1, 1); CP_COMMIT();
    RSTAGE2(2, 2); CP_COMMIT();

    // ---- epilogue 1: z = tanh(f)*sigmoid(g); 2-plane into SMEM z tile ----
#pragma unroll
    for (int j = 0; j < 4; j++) {
        int c0 = wc * 32 + j * 8 + (lane & 3) * 2;
        int ch = c0 >> 1;
        float bfv = 0.f, bgv = 0.f;
        if (ch < 120) { bfv = bf[layer * 120 + ch]; bgv = bg[layer * 120 + ch]; }
#pragma unroll
        for (int i = 0; i < 4; i++)
#pragma unroll
            for (int h = 0; h < 2; h++) {
                int row = wn * 64 + i * 16 + h * 8 + (lane >> 2);
                float z = gated_act(acc[i][j][h * 2] + bfv, acc[i][j][h * 2 + 1] + bgv);
                __half zh, zm; msplit(z, zh, zm);
                *reinterpret_cast<__half*>(sm + ZOFF + row * ZPIT + ch * 2) = zh;
                *reinterpret_cast<__half*>(sm + ZOFF + ZPL + row * ZPIT + ch * 2) = zm;
            }
    }

    __syncthreads();   // z tile complete
    // ---- coalesced z -> g_Z (hi plane), 16B per store, 4 per thread ----
    {
        __half* zg = g_Z + (size_t)layer * NTOT * 128 + (size_t)n0 * 128;
#pragma unroll
        for (int i = 0; i < 4; i++) {
            int u = tid + i * 512;              // 2048 units of 16B
            int row = u >> 4, o16 = u & 15;
            uint4 v = *reinterpret_cast<const uint4*>(sm + ZOFF + row * ZPIT + o16 * 16);
            *reinterpret_cast<uint4*>(zg + (size_t)row * 128 + o16 * 8) = v;
        }
    }

    // ---- RES GEMM: res[128t x 128ch] = z @ Wres^T (4 iterations, 2 chunks each) ----
    float racc[4][2][4];
#pragma unroll
    for (int i = 0; i < 4; i++)
#pragma unroll
        for (int j = 0; j < 2; j++)
#pragma unroll
            for (int k = 0; k < 4; k++) racc[i][j][k] = 0.f;

#pragma unroll 1
    for (int rc2 = 0; rc2 < 4; rc2++) {
        CP_WAIT2();
        __syncthreads();
        if (rc2 + 3 < 4) RSTAGE2(rc2 + 3, (rc2 + 3) & 3);
        CP_COMMIT();

        const uint32_t base = smb + (uint32_t)(rc2 & 3) * SLOT;
#pragma unroll
        for (int sub = 0; sub < 2; sub++) {
            int rc = 2 * rc2 + sub;
            const uint32_t sb = base + (uint32_t)sub * 12288u;
            uint32_t Z1[4][4], Z2[4][4], RB[4];
            uint32_t zk = (uint32_t)(rc * 32) + (lane >> 4) * 16;
#pragma unroll
            for (int i = 0; i < 4; i++) {
                uint32_t zr = smb + ZOFF + (wn * 64 + i * 16 + (lane & 15)) * ZPIT + zk;
                LDM4(Z1[i], zr);
                LDM4(Z2[i], zr + ZPL);
            }
            LDM4(RB, sb + offRB);
#pragma unroll
            for (int i = 0; i < 4; i++)
#pragma unroll
                for (int j = 0; j < 2; j++)
                    MMA(racc[i][j], Z1[i], RB[j * 2], RB[j * 2 + 1]);
            LDM4(RB, sb + 6144u + offRB);
#pragma unroll
            for (int i = 0; i < 4; i++)
#pragma unroll
                for (int j = 0; j < 2; j++)
                    MMA(racc[i][j], Z2[i], RB[j * 2], RB[j * 2 + 1]);
        }
    }
#undef RSTAGE2

    // ---- epilogue 2: X_next = (C1*Xh + Xm) + res + bres, split-stored ----
#pragma unroll
    for (int j = 0; j < 2; j++) {
        int col = wc * 16 + j * 8 + (lane & 3) * 2;
        if (col < 120) {
            float bv0 = bres[layer * 120 + col];
            float bv1 = bres[layer * 120 + col + 1];
#pragma unroll
            for (int i = 0; i < 4; i++)
#pragma unroll
                for (int h = 0; h < 2; h++) {
                    int row = n0 + wn * 64 + i * 16 + h * 8 + (lane >> 2);
                    size_t off = (size_t)row * 128 + col;
                    __half2 xh = *reinterpret_cast<const __half2*>(Xrh + off);
                    __half2 xm = *reinterpret_cast<const __half2*>(Xrm + off);
                    float x0 = C1 * __half2float(xh.x) + __half2float(xm.x)
                             + racc[i][j][h * 2] + bv0;
                    float x1 = C1 * __half2float(xh.y) + __half2float(xm.y)
                             + racc[i][j][h * 2 + 1] + bv1;
                    __half h0, m0, h1, m1;
                    msplit(x0, h0, m0); msplit(x1, h1, m1);
                    __half2 hp; hp.x = h0; hp.y = h1;
                    __half2 mp; mp.x = m0; mp.y = m1;
                    *reinterpret_cast<__half2*>(Xwh + off) = hp;
                    *reinterpret_cast<__half2*>(Xwm + off) = mp;
                }
        }
    }
}

// ---------------- generic GEMM: CTA 128 x 256, 512 thr, 4 stages ----------------
// MODE 2 = SKIP (PLANES=1, 2 chunks/iter), MODE 3 = H1, MODE 4 = H2 (PLANES=2, 1 chunk/iter).
template<int MODE, int ITERS, int PLANES>
__global__ void __launch_bounds__(512, 1) mma_kernel(const float* __restrict__ bA,
                                                     float* __restrict__ dout) {
    extern __shared__ __align__(16) char sm[];
    const int tid = threadIdx.x, lane = tid & 31, wid = tid >> 5;
    const int wn = wid >> 3, wc = wid & 7;
    const int n0 = blockIdx.x * 128;
    const uint32_t smb = smem_u32(sm);

    const __half *APh, *APm;
    if (MODE == 3) { APh = g_ShP; APm = g_SmP; }
    else           { APh = g_HhP; APm = g_HmP; }
    const __half* Wf2 = (MODE == 3) ? g_W1b : g_W2b;

    uint32_t offA[4], offB[2];
    {
        int rA = wn * 64 + (lane & 15);
        int cA = (lane >> 4) * 16;
#pragma unroll
        for (int i = 0; i < 4; i++) offA[i] = (uint32_t)((rA + i * 16) * 48 + cA);
        int rB = wc * 32 + (lane >> 4) * 8 + (lane & 7);
        int cB = ((lane >> 3) & 1) * 16;
        offB[0] = (uint32_t)(rB * 48 + cB);
        offB[1] = (uint32_t)((rB + 16) * 48 + cB);
    }

    float acc[4][4][4];
#pragma unroll
    for (int i = 0; i < 4; i++)
#pragma unroll
        for (int j = 0; j < 4; j++)
#pragma unroll
            for (int k = 0; k < 4; k++) acc[i][j][k] = 0.f;

// heads: 1 chunk per slot (A 2-plane @0/6144, W 2-plane @12288/24576), slot 36864
#define HSTAGE(cc, s) do {                                                        \
        {                                                                         \
            int p = tid >> 8, r = (tid >> 1) & 127, hh = tid & 1;                 \
            const __half* ap = p ? APm : APh;                                     \
            uint32_t d = smb + (s) * 36864u + p * 6144u + r * 48u + hh * 16u;     \
            CPA16(d, ap + (size_t)(n0 + r) * 256 + (cc) * 16 + hh * 8, 16);       \
        }                                                                         \
        _Pragma("unroll")                                                         \
        for (int ii = 0; ii < 2; ii++) {                                          \
            int u = tid + ii * 512, p = (u >> 9) & 1, r = (u >> 1) & 255, hh = u & 1; \
            uint32_t d = smb + (s) * 36864u + 12288u + p * 12288u + r * 48u + hh * 16u; \
            const __half* sp = Wf2 + ((size_t)((r >> 7) * 16 + (cc))) * 4096      \
                               + p * 2048 + (r & 127) * 16 + hh * 8;              \
            CPA16(d, sp, 16);                                                     \
        }                                                                         \
    } while (0)

// skip: 2 chunks per slot (sub regions of 18432: A@0, W@6144), slot 36864
#define SSTAGE(it, s) do {                                                        \
        _Pragma("unroll")                                                         \
        for (int sub = 0; sub < 2; sub++) {                                       \
            int cc = 2 * (it) + sub;                                              \
            uint32_t rb = smb + (s) * 36864u + sub * 18432u;                      \
            if (tid < 256) {                                                      \
                int r = tid >> 1, hh = tid & 1;                                   \
                const __half* ap = g_Z + (size_t)(cc >> 3) * NTOT * 128;          \
                CPA16(rb + r * 48u + hh * 16u,                                    \
                      ap + (size_t)(n0 + r) * 128 + (cc & 7) * 16 + hh * 8, 16);  \
            }                                                                     \
            {                                                                     \
                int r = (tid >> 1) & 255, hh = tid & 1;                           \
                const __half* sp = g_WSK + ((size_t)((r >> 7) * 128 + cc)) * 2048 \
                                   + (r & 127) * 16 + hh * 8;                     \
                CPA16(rb + 6144u + r * 48u + hh * 16u, sp, 16);                   \
            }                                                                     \
        }                                                                         \
    } while (0)

    if (PLANES == 2) { HSTAGE(0, 0); CP_COMMIT(); HSTAGE(1, 1); CP_COMMIT(); HSTAGE(2, 2); CP_COMMIT(); }
    else             { SSTAGE(0, 0); CP_COMMIT(); SSTAGE(1, 1); CP_COMMIT(); SSTAGE(2, 2); CP_COMMIT(); }

#pragma unroll 1
    for (int c = 0; c < ITERS; c++) {
        CP_WAIT2();
        __syncthreads();
        if (c + 3 < ITERS) { if (PLANES == 2) HSTAGE(c + 3, (c + 3) & 3); else SSTAGE(c + 3, (c + 3) & 3); }
        CP_COMMIT();

        const uint32_t base = smb + (uint32_t)(c & 3) * 36864u;
        if (PLANES == 2) {
            uint32_t A1[4][4], A2[4][4], Bf[2][4];
#pragma unroll
            for (int i = 0; i < 4; i++) {
                LDM4(A1[i], base + offA[i]);
                LDM4(A2[i], base + 6144u + offA[i]);
            }
            LDM4(Bf[0], base + 12288u + offB[0]);
            LDM4(Bf[1], base + 12288u + offB[1]);
#pragma unroll
            for (int i = 0; i < 4; i++)
#pragma unroll
                for (int j = 0; j < 4; j++)
                    MMA(acc[i][j], A1[i], Bf[j >> 1][(j & 1) * 2], Bf[j >> 1][(j & 1) * 2 + 1]);
            LDM4(Bf[0], base + 24576u + offB[0]);
            LDM4(Bf[1], base + 24576u + offB[1]);
#pragma unroll
            for (int i = 0; i < 4; i++)
#pragma unroll
                for (int j = 0; j < 4; j++)
                    MMA(acc[i][j], A2[i], Bf[j >> 1][(j & 1) * 2], Bf[j >> 1][(j & 1) * 2 + 1]);
        } else {
#pragma unroll
            for (int sub = 0; sub < 2; sub++) {
                const uint32_t sb = base + (uint32_t)sub * 18432u;
                uint32_t Af[4][4], Bf[2][4];
#pragma unroll
                for (int i = 0; i < 4; i++) LDM4(Af[i], sb + offA[i]);
                LDM4(Bf[0], sb + 6144u + offB[0]);
                LDM4(Bf[1], sb + 6144u + offB[1]);
#pragma unroll
                for (int i = 0; i < 4; i++)
#pragma unroll
                    for (int j = 0; j < 4; j++)
                        MMA(acc[i][j], Af[i], Bf[j >> 1][(j & 1) * 2], Bf[j >> 1][(j & 1) * 2 + 1]);
            }
        }
    }
#undef HSTAGE
#undef SSTAGE

#pragma unroll
    for (int j = 0; j < 4; j++) {
        const int col = wc * 32 + j * 8 + (lane & 3) * 2;
        float bv0, bv1;
        if (MODE == 2) { bv0 = g_Bsk[col]; bv1 = g_Bsk[col + 1]; }
        else           { bv0 = bA[col]; bv1 = bA[col + 1]; }
#pragma unroll
        for (int i = 0; i < 4; i++)
#pragma unroll
            for (int h = 0; h < 2; h++) {
                int na = n0 + wn * 64 + i * 16 + h * 8 + (lane >> 2);
                float v0 = acc[i][j][h * 2] + bv0;
                float v1 = acc[i][j][h * 2 + 1] + bv1;
                if (MODE == 2 || MODE == 3) {
                    float r0 = fmaxf(v0, 0.f), r1 = fmaxf(v1, 0.f);
                    __half h0, m0, h1, m1;
                    msplit(r0, h0, m0); msplit(r1, h1, m1);
                    __half2 hp; hp.x = h0; hp.y = h1;
                    __half2 mp; mp.x = m0; mp.y = m1;
                    __half* Oh = (MODE == 2) ? g_ShP : g_HhP;
                    __half* Om = (MODE == 2) ? g_SmP : g_HmP;
                    *reinterpret_cast<__half2*>(Oh + (size_t)na * 256 + col) = hp;
                    *reinterpret_cast<__half2*>(Om + (size_t)na * 256 + col) = mp;
                } else {
                    int b = na >> 14, t = na & (T_LEN - 1);
                    dout[((size_t)b * 256 + col) * T_LEN + t]     = v0;
                    dout[((size_t)b * 256 + col + 1) * T_LEN + t] = v1;
                }
            }
    }
}

// ---------------- launch ----------------
extern "C" void kernel_launch(void* const* d_in, const int* in_sizes, int n_in,
                              void* d_out, int out_size) {
    const float* wave  = (const float*)d_in[0];
    const float* W_in  = (const float*)d_in[1];
    const float* b_in  = (const float*)d_in[2];
    const float* Wf    = (const float*)d_in[3];
    const float* bf    = (const float*)d_in[4];
    const float* Wg    = (const float*)d_in[5];
    const float* bg    = (const float*)d_in[6];
    const float* Wres  = (const float*)d_in[7];
    const float* bres  = (const float*)d_in[8];
    const float* Wskip = (const float*)d_in[9];
    const float* bskip = (const float*)d_in[10];
    const float* W1    = (const float*)d_in[11];
    const float* b1    = (const float*)d_in[12];
    const float* W2    = (const float*)d_in[13];
    const float* b2    = (const float*)d_in[14];
    float* out = (float*)d_out;

    const int GS = 4 * 36864;   // 147456
    cudaFuncSetAttribute(fgres_kernel, cudaFuncAttributeMaxDynamicSharedMemorySize, FS_BYTES);
    cudaFuncSetAttribute(mma_kernel<2, 64, 1>, cudaFuncAttributeMaxDynamicSharedMemorySize, GS);
    cudaFuncSetAttribute(mma_kernel<3, 16, 2>, cudaFuncAttributeMaxDynamicSharedMemorySize, GS);
    cudaFuncSetAttribute(mma_kernel<4, 16, 2>, cudaFuncAttributeMaxDynamicSharedMemorySize, GS);

    pack_fg<<<16 * 2 * 16 * 2048 / 256, 256>>>(Wf, Wg);
    pack_rs<<<16 * 8 * 2048 / 256, 256>>>(Wres);
    pack_sk<<<2 * 128 * 2048 / 256, 256>>>(Wskip, bskip);
    pack_h <<<2 * 16 * 2048 / 256, 256>>>(W1, W2);
    init_kernel<<<(size_t)NTOT * 128 / 256, 256>>>(wave, W_in, b_in);

    static const int dil[NBLK] = {1, 2, 4, 8, 16, 32, 64, 128,
                                  1, 2, 4, 8, 16, 32, 64, 128};

    for (int i = 0; i < NBLK; i++)
        fgres_kernel<<<NTOT / 128, 512, FS_BYTES>>>(i, dil[i], bf, bg, bres);

    mma_kernel<2, 64, 1><<<NTOT / 128, 512, GS>>>(nullptr, nullptr);   // skip (2 chunks/iter)
    mma_kernel<3, 16, 2><<<NTOT / 128, 512, GS>>>(b1, nullptr);        // head1
    mma_kernel<4, 16, 2><<<NTOT / 128, 512, GS>>>(b2, out);            // head2
}

// round 16
// speedup vs baseline: 2.3270x; 1.0157x over previous
#include <cuda_runtime.h>
#include <cuda_fp16.h>
#include <cstdint>
#include <cstddef>

#define T_LEN 16384
#define NTOT  131072
#define NBLK  16

#define DELTA 0.015625f     // 2^-6
#define C1    0.984375f     // 1 - 2^-6

// ---------------- activations, time-major [n][ch] ----------------
__device__ __align__(16) __half g_Xh[2][(size_t)NTOT * 128];
__device__ __align__(16) __half g_Xm[2][(size_t)NTOT * 128];
__device__ __align__(16) __half g_Z [(size_t)NBLK * NTOT * 128];  // single fp16 (skip input)
__device__ __align__(16) __half g_ShP[(size_t)NTOT * 256];
__device__ __align__(16) __half g_SmP[(size_t)NTOT * 256];
__device__ __align__(16) __half g_HhP[(size_t)NTOT * 256];
__device__ __align__(16) __half g_HmP[(size_t)NTOT * 256];

// weight blocks. FG: K repacked to 240 (tap1 120 || tap0 120) = 15 chunks.
__device__ __align__(16) __half g_WFG[(size_t)NBLK * 2 * 15 * 4096];
__device__ __align__(16) __half g_WRS[(size_t)NBLK * 8 * 4096];
__device__ __align__(16) __half g_WSK[(size_t)2 * 128 * 2048];    // single fp16
__device__ __align__(16) __half g_W1b[(size_t)2 * 15 * 4096];     // K=240 exact, 15 chunks
__device__ __align__(16) __half g_W2b[(size_t)2 * 16 * 4096];
__device__ float g_Bsk[256];

// ---------------- helpers ----------------
__device__ __forceinline__ uint32_t smem_u32(const void* p) {
    uint32_t a;
    asm("{ .reg .u64 t; cvta.to.shared.u64 t, %1; cvt.u32.u64 %0, t; }" : "=r"(a) : "l"(p));
    return a;
}
__device__ __forceinline__ void msplit(float v, __half& h, __half& m) {
    h = __float2half(v);
    float hf = __half2float(h);
    m = __float2half(DELTA * hf + (v - hf));
}
__device__ __forceinline__ void wsplit(float v, __half& w1, __half& w2) {
    w1 = __float2half(C1 * v);
    float w1f = __half2float(w1);
    w2 = __float2half((v - w1f) * 64.0f);
}
__device__ __forceinline__ float gated_act(float f, float g) {
    float ef = __expf(-2.0f * fabsf(f));
    float eg = __expf(-g);
    float z = (1.0f - ef) * __fdividef(1.0f, (1.0f + ef) * (1.0f + eg));
    return copysignf(z, f);
}

// ---------------- packing ----------------
// FG virtual K: vch 0..119 = tap1 (x[t]), 120..239 = tap0 (x[t-d]); 15 chunks of 16.
__global__ void pack_fg(const float* __restrict__ Wf, const float* __restrict__ Wg) {
    int idx = blockIdx.x * blockDim.x + threadIdx.x;     // NBLK*2*15*4096
    int kin = idx & 15, row = (idx >> 4) & 127;
    int blk = idx >> 11;
    int c = blk % 15, nt = (blk / 15) & 1, l = blk / 30;
    int m = nt * 128 + row, ch = m >> 1, isg = m & 1;
    int vch = c * 16 + kin;
    int tap = (vch < 120) ? 1 : 0;
    int cin = tap ? vch : vch - 120;
    float v = 0.f;
    if (ch < 120) {
        const float* s = isg ? Wg : Wf;
        v = s[(((size_t)l * 120 + ch) * 120 + cin) * 2 + tap];
    }
    __half h, mo; wsplit(v, h, mo);
    __half* b = g_WFG + ((size_t)((l * 2 + nt) * 15 + c)) * 4096;
    b[row * 16 + kin] = h;
    b[2048 + row * 16 + kin] = mo;
}

__global__ void pack_rs(const float* __restrict__ Wres) {
    int idx = blockIdx.x * blockDim.x + threadIdx.x;
    int kin = idx & 15, row = (idx >> 4) & 127, c = (idx >> 11) & 7, l = idx >> 14;
    int cin = c * 16 + kin;
    float v = (row < 120 && cin < 120) ? Wres[((size_t)l * 120 + row) * 120 + cin] : 0.f;
    __half h, mo; wsplit(v, h, mo);
    __half* blk = g_WRS + ((size_t)(l * 8 + c)) * 4096;
    blk[row * 16 + kin] = h;
    blk[2048 + row * 16 + kin] = mo;
}

__global__ void pack_sk(const float* __restrict__ Wskip, const float* __restrict__ bskip) {
    int idx = blockIdx.x * blockDim.x + threadIdx.x;   // 2*128*2048
    int kin = idx & 15, row = (idx >> 4) & 127, c = (idx >> 11) & 127, nt = idx >> 18;
    int q = nt * 128 + row, lay = c >> 3, cin = (c & 7) * 16 + kin;
    float v = (q < 240 && cin < 120) ? Wskip[((size_t)lay * 240 + q) * 120 + cin] : 0.f;
    g_WSK[((size_t)(nt * 128 + c)) * 2048 + row * 16 + kin] = __float2half(v);
    if (idx < 256) {
        float s = 0.f;
        if (idx < 240) for (int j = 0; j < NBLK; j++) s += bskip[j * 240 + idx];
        g_Bsk[idx] = s;
    }
}

__global__ void pack_h(const float* __restrict__ W1, const float* __restrict__ W2) {
    int idx = blockIdx.x * blockDim.x + threadIdx.x;   // 2*16*2048
    int kin = idx & 15, row = (idx >> 4) & 127, c = (idx >> 11) & 15, nt = idx >> 15;
    int q = nt * 128 + row, k = c * 16 + kin;
    __half h, mo;
    if (c < 15) {   // W1: K=240 exact, 15 chunks
        wsplit(W1[(size_t)q * 240 + k], h, mo);
        __half* b1 = g_W1b + ((size_t)(nt * 15 + c)) * 4096;
        b1[row * 16 + kin] = h; b1[2048 + row * 16 + kin] = mo;
    }
    wsplit(W2[(size_t)q * 256 + k], h, mo);
    __half* b2 = g_W2b + ((size_t)(nt * 16 + c)) * 4096;
    b2[row * 16 + kin] = h; b2[2048 + row * 16 + kin] = mo;
}

__global__ void init_kernel(const float* __restrict__ wave,
                            const float* __restrict__ W_in,
                            const float* __restrict__ b_in) {
    int idx = blockIdx.x * blockDim.x + threadIdx.x;
    int n = idx >> 7, c = idx & 127;
    float x = (c < 120) ? (W_in[c] * wave[n] + b_in[c]) : 0.f;
    __half h, m; msplit(x, h, m);
    g_Xh[0][idx] = h; g_Xm[0][idx] = m;
}

// ---------------- asm macros ----------------
#define CPA16(dst, src, sz) \
    asm volatile("cp.async.cg.shared.global [%0], [%1], 16, %2;" \
                 :: "r"(dst), "l"(src), "r"(sz) : "memory")
#define CPA8(dst, src) \
    asm volatile("cp.async.ca.shared.global [%0], [%1], 8;" \
                 :: "r"(dst), "l"(src) : "memory")
#define CP_COMMIT() asm volatile("cp.async.commit_group;" ::: "memory")
#define CP_WAIT2()  asm volatile("cp.async.wait_group 2;" ::: "memory")

#define LDM4(rr, addr) \
    asm volatile("ldmatrix.sync.aligned.m8n8.x4.shared.b16 {%0,%1,%2,%3}, [%4];" \
                 : "=r"((rr)[0]), "=r"((rr)[1]), "=r"((rr)[2]), "=r"((rr)[3]) : "r"(addr))

#define MMA(cr, a, b0v, b1v) \
    asm volatile("mma.sync.aligned.m16n8k16.row.col.f32.f16.f16.f32 " \
                 "{%0,%1,%2,%3}, {%4,%5,%6,%7}, {%8,%9}, {%0,%1,%2,%3};" \
                 : "+f"((cr)[0]), "+f"((cr)[1]), "+f"((cr)[2]), "+f"((cr)[3]) \
                 : "r"((a)[0]), "r"((a)[1]), "r"((a)[2]), "r"((a)[3]), "r"(b0v), "r"(b1v))

// ---------------- fused FG + RES kernel: CTA 128(time) x 256(col), 512 thr, 4 stages ----------------
// Stage slot (36864B): Ah@0(6144) Am@6144 W1@12288(12288) W2@24576.
// z tile planes: zh@147456 (34816B), zm@+34816. pitch 272.
#define SLOT  36864u
#define ZOFF  147456u
#define ZPIT  272u
#define ZPL   34816u
#define FS_BYTES (147456 + 2 * 34816)   // 217088

__global__ void __launch_bounds__(512, 1) fgres_kernel(int layer, int dil,
        const float* __restrict__ bf, const float* __restrict__ bg,
        const float* __restrict__ bres) {
    extern __shared__ __align__(16) char sm[];
    const int tid = threadIdx.x, lane = tid & 31, wid = tid >> 5;
    const int wn = wid >> 3, wc = wid & 7;      // 2 time-groups(64) x 8 col-groups(32)
    const int n0 = blockIdx.x * 128;
    const uint32_t smb = smem_u32(sm);

    const __half* Xrh = g_Xh[layer & 1];
    const __half* Xrm = g_Xm[layer & 1];
    __half* Xwh = g_Xh[(layer + 1) & 1];
    __half* Xwm = g_Xm[(layer + 1) & 1];
    const __half* Wb  = g_WFG + (size_t)layer * 2 * 15 * 4096;
    const __half* WRb = g_WRS + (size_t)layer * 8 * 4096;

    uint32_t offA[4], offB[2], offRB;
    {
        int rA = wn * 64 + (lane & 15);
        int cA = (lane >> 4) * 16;
#pragma unroll
        for (int i = 0; i < 4; i++) offA[i] = (uint32_t)((rA + i * 16) * 48 + cA);
        int rB = wc * 32 + (lane >> 4) * 8 + (lane & 7);
        int cB = ((lane >> 3) & 1) * 16;
        offB[0] = (uint32_t)(rB * 48 + cB);
        offB[1] = (uint32_t)((rB + 16) * 48 + cB);
        int rR = wc * 16 + (lane >> 4) * 8 + (lane & 7);
        offRB = (uint32_t)(rR * 48 + cB);
    }

    float acc[4][4][4];
#pragma unroll
    for (int i = 0; i < 4; i++)
#pragma unroll
        for (int j = 0; j < 4; j++)
#pragma unroll
            for (int k = 0; k < 4; k++) acc[i][j][k] = 0.f;

// A granule: 16B = 8 virtual channels at vch0 = cc*16 + hh*8.
// vch0 < 120 -> tap1 (x[n]); vch0 >= 120 -> tap0 (x[n-d], causal zfill).
#define FSTAGE(cc, s) do {                                                        \
        {                                                                         \
            int p = tid >> 8, r = (tid >> 1) & 127, hh = tid & 1;                 \
            int na = n0 + r, nn = na, sz = 16;                                    \
            int vch0 = (cc) * 16 + hh * 8, ch0 = vch0;                            \
            if (vch0 >= 120) {                                                    \
                ch0 = vch0 - 120;                                                 \
                int t = na & (T_LEN - 1);                                         \
                if (t >= dil) nn = na - dil; else sz = 0;                         \
            }                                                                     \
            uint32_t d = smb + (s) * SLOT + p * 6144u + r * 48u + hh * 16u;       \
            const __half* gp = (p ? Xrm : Xrh) + (size_t)nn * 128 + ch0;          \
            CPA16(d, gp, sz);                                                     \
        }                                                                         \
        _Pragma("unroll")                                                         \
        for (int ii = 0; ii < 2; ii++) {                                          \
            int u = tid + ii * 512, p = (u >> 9) & 1, r = (u >> 1) & 255, hh = u & 1; \
            uint32_t d = smb + (s) * SLOT + 12288u + p * 12288u + r * 48u + hh * 16u; \
            const __half* sp = Wb + ((size_t)((r >> 7) * 15 + (cc))) * 4096       \
                               + p * 2048 + (r & 127) * 16 + hh * 8;              \
            CPA16(d, sp, 16);                                                     \
        }                                                                         \
    } while (0)

    FSTAGE(0, 0); CP_COMMIT();
    FSTAGE(1, 1); CP_COMMIT();
    FSTAGE(2, 2); CP_COMMIT();

#pragma unroll 1
    for (int c = 0; c < 15; c++) {
        CP_WAIT2();
        __syncthreads();
        if (c + 3 < 15) FSTAGE(c + 3, (c + 3) & 3);
        CP_COMMIT();

        const uint32_t base = smb + (uint32_t)(c & 3) * SLOT;
        uint32_t A1[4][4], A2[4][4], Bf[2][4];
#pragma unroll
        for (int i = 0; i < 4; i++) {
            LDM4(A1[i], base + offA[i]);
            LDM4(A2[i], base + 6144u + offA[i]);
        }
        LDM4(Bf[0], base + 12288u + offB[0]);
        LDM4(Bf[1], base + 12288u + offB[1]);
#pragma unroll
        for (int i = 0; i < 4; i++)
#pragma unroll
            for (int j = 0; j < 4; j++)
                MMA(acc[i][j], A1[i], Bf[j >> 1][(j & 1) * 2], Bf[j >> 1][(j & 1) * 2 + 1]);
        LDM4(Bf[0], base + 24576u + offB[0]);
        LDM4(Bf[1], base + 24576u + offB[1]);
#pragma unroll
        for (int i = 0; i < 4; i++)
#pragma unroll
            for (int j = 0; j < 4; j++)
                MMA(acc[i][j], A2[i], Bf[j >> 1][(j & 1) * 2], Bf[j >> 1][(j & 1) * 2 + 1]);
    }
#undef FSTAGE

    // RES W prefetch: 2 chunks per slot (chunk sub at +sub*12288; planes at +0 / +6144)
#define RSTAGE2(rc2, s) do {                                                      \
        _Pragma("unroll")                                                         \
        for (int sub = 0; sub < 2; sub++) {                                       \
            int rc = 2 * (rc2) + sub;                                             \
            int p = tid >> 8, r = (tid >> 1) & 127, hh = tid & 1;                 \
            uint32_t d = smb + (s) * SLOT + sub * 12288u + p * 6144u + r * 48u + hh * 16u; \
            const __half* sp = WRb + (size_t)rc * 4096 + p * 2048 + r * 16 + hh * 8; \
            CPA16(d, sp, 16);                                                     \
        }                                                                         \
    } while (0)

    __syncthreads();   // all FG reads of all slots done before RES W overwrites
    RSTAGE2(0, 0); CP_COMMIT();
    RSTAGE2(1, 1); CP_COMMIT();
    RSTAGE2(2, 2); CP_COMMIT();

    // ---- epilogue 1: z = tanh(f)*sigmoid(g); 2-plane into SMEM z tile ----
#pragma unroll
    for (int j = 0; j < 4; j++) {
        int c0 = wc * 32 + j * 8 + (lane & 3) * 2;
        int ch = c0 >> 1;
        float bfv = 0.f, bgv = 0.f;
        if (ch < 120) { bfv = bf[layer * 120 + ch]; bgv = bg[layer * 120 + ch]; }
#pragma unroll
        for (int i = 0; i < 4; i++)
#pragma unroll
            for (int h = 0; h < 2; h++) {
                int row = wn * 64 + i * 16 + h * 8 + (lane >> 2);
                float z = gated_act(acc[i][j][h * 2] + bfv, acc[i][j][h * 2 + 1] + bgv);
                __half zh, zm; msplit(z, zh, zm);
                *reinterpret_cast<__half*>(sm + ZOFF + row * ZPIT + ch * 2) = zh;
                *reinterpret_cast<__half*>(sm + ZOFF + ZPL + row * ZPIT + ch * 2) = zm;
            }
    }

    __syncthreads();   // z tile complete
    // ---- coalesced z -> g_Z (hi plane), 16B per store, 4 per thread ----
    {
        __half* zg = g_Z + (size_t)layer * NTOT * 128 + (size_t)n0 * 128;
#pragma unroll
        for (int i = 0; i < 4; i++) {
            int u = tid + i * 512;              // 2048 units of 16B
            int row = u >> 4, o16 = u & 15;
            uint4 v = *reinterpret_cast<const uint4*>(sm + ZOFF + row * ZPIT + o16 * 16);
            *reinterpret_cast<uint4*>(zg + (size_t)row * 128 + o16 * 8) = v;
        }
    }

    // ---- RES GEMM: res[128t x 128ch] = z @ Wres^T (4 iterations, 2 chunks each) ----
    float racc[4][2][4];
#pragma unroll
    for (int i = 0; i < 4; i++)
#pragma unroll
        for (int j = 0; j < 2; j++)
#pragma unroll
            for (int k = 0; k < 4; k++) racc[i][j][k] = 0.f;

#pragma unroll 1
    for (int rc2 = 0; rc2 < 4; rc2++) {
        CP_WAIT2();
        __syncthreads();
        if (rc2 + 3 < 4) RSTAGE2(rc2 + 3, (rc2 + 3) & 3);
        CP_COMMIT();

        const uint32_t base = smb + (uint32_t)(rc2 & 3) * SLOT;
#pragma unroll
        for (int sub = 0; sub < 2; sub++) {
            int rc = 2 * rc2 + sub;
            const uint32_t sb = base + (uint32_t)sub * 12288u;
            uint32_t Z1[4][4], Z2[4][4], RB[4];
            uint32_t zk = (uint32_t)(rc * 32) + (lane >> 4) * 16;
#pragma unroll
            for (int i = 0; i < 4; i++) {
                uint32_t zr = smb + ZOFF + (wn * 64 + i * 16 + (lane & 15)) * ZPIT + zk;
                LDM4(Z1[i], zr);
                LDM4(Z2[i], zr + ZPL);
            }
            LDM4(RB, sb + offRB);
#pragma unroll
            for (int i = 0; i < 4; i++)
#pragma unroll
                for (int j = 0; j < 2; j++)
                    MMA(racc[i][j], Z1[i], RB[j * 2], RB[j * 2 + 1]);
            LDM4(RB, sb + 6144u + offRB);
#pragma unroll
            for (int i = 0; i < 4; i++)
#pragma unroll
                for (int j = 0; j < 2; j++)
                    MMA(racc[i][j], Z2[i], RB[j * 2], RB[j * 2 + 1]);
        }
    }
#undef RSTAGE2

    // ---- epilogue 2: X_next = (C1*Xh + Xm) + res + bres, split-stored ----
#pragma unroll
    for (int j = 0; j < 2; j++) {
        int col = wc * 16 + j * 8 + (lane & 3) * 2;
        if (col < 120) {
            float bv0 = bres[layer * 120 + col];
            float bv1 = bres[layer * 120 + col + 1];
#pragma unroll
            for (int i = 0; i < 4; i++)
#pragma unroll
                for (int h = 0; h < 2; h++) {
                    int row = n0 + wn * 64 + i * 16 + h * 8 + (lane >> 2);
                    size_t off = (size_t)row * 128 + col;
                    __half2 xh = *reinterpret_cast<const __half2*>(Xrh + off);
                    __half2 xm = *reinterpret_cast<const __half2*>(Xrm + off);
                    float x0 = C1 * __half2float(xh.x) + __half2float(xm.x)
                             + racc[i][j][h * 2] + bv0;
                    float x1 = C1 * __half2float(xh.y) + __half2float(xm.y)
                             + racc[i][j][h * 2 + 1] + bv1;
                    __half h0, m0, h1, m1;
                    msplit(x0, h0, m0); msplit(x1, h1, m1);
                    __half2 hp; hp.x = h0; hp.y = h1;
                    __half2 mp; mp.x = m0; mp.y = m1;
                    *reinterpret_cast<__half2*>(Xwh + off) = hp;
                    *reinterpret_cast<__half2*>(Xwm + off) = mp;
                }
        }
    }
}

// ---------------- generic GEMM: CTA 128 x 256, 512 thr, 4 stages ----------------
// MODE 2 = SKIP (PLANES=1, 2 chunks/iter), MODE 3 = H1 (15 chunks), MODE 4 = H2 (16).
template<int MODE, int ITERS, int PLANES>
__global__ void __launch_bounds__(512, 1) mma_kernel(const float* __restrict__ bA,
                                                     float* __restrict__ dout) {
    extern __shared__ __align__(16) char sm[];
    const int tid = threadIdx.x, lane = tid & 31, wid = tid >> 5;
    const int wn = wid >> 3, wc = wid & 7;
    const int n0 = blockIdx.x * 128;
    const uint32_t smb = smem_u32(sm);

    const __half *APh, *APm;
    if (MODE == 3) { APh = g_ShP; APm = g_SmP; }
    else           { APh = g_HhP; APm = g_HmP; }
    const __half* Wf2 = (MODE == 3) ? g_W1b : g_W2b;

    uint32_t offA[4], offB[2];
    {
        int rA = wn * 64 + (lane & 15);
        int cA = (lane >> 4) * 16;
#pragma unroll
        for (int i = 0; i < 4; i++) offA[i] = (uint32_t)((rA + i * 16) * 48 + cA);
        int rB = wc * 32 + (lane >> 4) * 8 + (lane & 7);
        int cB = ((lane >> 3) & 1) * 16;
        offB[0] = (uint32_t)(rB * 48 + cB);
        offB[1] = (uint32_t)((rB + 16) * 48 + cB);
    }

    float acc[4][4][4];
#pragma unroll
    for (int i = 0; i < 4; i++)
#pragma unroll
        for (int j = 0; j < 4; j++)
#pragma unroll
            for (int k = 0; k < 4; k++) acc[i][j][k] = 0.f;

// heads: 1 chunk per slot (A 2-plane @0/6144, W 2-plane @12288/24576); W block stride = ITERS
#define HSTAGE(cc, s) do {                                                        \
        {                                                                         \
            int p = tid >> 8, r = (tid >> 1) & 127, hh = tid & 1;                 \
            const __half* ap = p ? APm : APh;                                     \
            uint32_t d = smb + (s) * 36864u + p * 6144u + r * 48u + hh * 16u;     \
            CPA16(d, ap + (size_t)(n0 + r) * 256 + (cc) * 16 + hh * 8, 16);       \
        }                                                                         \
        _Pragma("unroll")                                                         \
        for (int ii = 0; ii < 2; ii++) {                                          \
            int u = tid + ii * 512, p = (u >> 9) & 1, r = (u >> 1) & 255, hh = u & 1; \
            uint32_t d = smb + (s) * 36864u + 12288u + p * 12288u + r * 48u + hh * 16u; \
            const __half* sp = Wf2 + ((size_t)((r >> 7) * ITERS + (cc))) * 4096   \
                               + p * 2048 + (r & 127) * 16 + hh * 8;              \
            CPA16(d, sp, 16);                                                     \
        }                                                                         \
    } while (0)

// skip: 2 chunks per slot (sub regions of 18432: A@0, W@6144); A spread over 512 thr (8B)
#define SSTAGE(it, s) do {                                                        \
        _Pragma("unroll")                                                         \
        for (int sub = 0; sub < 2; sub++) {                                       \
            int cc = 2 * (it) + sub;                                              \
            uint32_t rb = smb + (s) * 36864u + sub * 18432u;                      \
            {                                                                     \
                int r = tid >> 2, q = tid & 3;                                    \
                const __half* ap = g_Z + (size_t)(cc >> 3) * NTOT * 128;          \
                CPA8(rb + r * 48u + q * 8u,                                       \
                     ap + (size_t)(n0 + r) * 128 + (cc & 7) * 16 + q * 4);        \
            }                                                                     \
            {                                                                     \
                int r = (tid >> 1) & 255, hh = tid & 1;                           \
                const __half* sp = g_WSK + ((size_t)((r >> 7) * 128 + cc)) * 2048 \
                                   + (r & 127) * 16 + hh * 8;                     \
                CPA16(rb + 6144u + r * 48u + hh * 16u, sp, 16);                   \
            }                                                                     \
        }                                                                         \
    } while (0)

    if (PLANES == 2) { HSTAGE(0, 0); CP_COMMIT(); HSTAGE(1, 1); CP_COMMIT(); HSTAGE(2, 2); CP_COMMIT(); }
    else             { SSTAGE(0, 0); CP_COMMIT(); SSTAGE(1, 1); CP_COMMIT(); SSTAGE(2, 2); CP_COMMIT(); }

#pragma unroll 1
    for (int c = 0; c < ITERS; c++) {
        CP_WAIT2();
        __syncthreads();
        if (c + 3 < ITERS) { if (PLANES == 2) HSTAGE(c + 3, (c + 3) & 3); else SSTAGE(c + 3, (c + 3) & 3); }
        CP_COMMIT();

        const uint32_t base = smb + (uint32_t)(c & 3) * 36864u;
        if (PLANES == 2) {
            uint32_t A1[4][4], A2[4][4], Bf[2][4];
#pragma unroll
            for (int i = 0; i < 4; i++) {
                LDM4(A1[i], base + offA[i]);
                LDM4(A2[i], base + 6144u + offA[i]);
            }
            LDM4(Bf[0], base + 12288u + offB[0]);
            LDM4(Bf[1], base + 12288u + offB[1]);
#pragma unroll
            for (int i = 0; i < 4; i++)
#pragma unroll
                for (int j = 0; j < 4; j++)
                    MMA(acc[i][j], A1[i], Bf[j >> 1][(j & 1) * 2], Bf[j >> 1][(j & 1) * 2 + 1]);
            LDM4(Bf[0], base + 24576u + offB[0]);
            LDM4(Bf[1], base + 24576u + offB[1]);
#pragma unroll
            for (int i = 0; i < 4; i++)
#pragma unroll
                for (int j = 0; j < 4; j++)
                    MMA(acc[i][j], A2[i], Bf[j >> 1][(j & 1) * 2], Bf[j >> 1][(j & 1) * 2 + 1]);
        } else {
#pragma unroll
            for (int sub = 0; sub < 2; sub++) {
                const uint32_t sb = base + (uint32_t)sub * 18432u;
                uint32_t Af[4][4], Bf[2][4];
#pragma unroll
                for (int i = 0; i < 4; i++) LDM4(Af[i], sb + offA[i]);
                LDM4(Bf[0], sb + 6144u + offB[0]);
                LDM4(Bf[1], sb + 6144u + offB[1]);
#pragma unroll
                for (int i = 0; i < 4; i++)
#pragma unroll
                    for (int j = 0; j < 4; j++)
                        MMA(acc[i][j], Af[i], Bf[j >> 1][(j & 1) * 2], Bf[j >> 1][(j & 1) * 2 + 1]);
            }
        }
    }
#undef HSTAGE
#undef SSTAGE

#pragma unroll
    for (int j = 0; j < 4; j++) {
        const int col = wc * 32 + j * 8 + (lane & 3) * 2;
        float bv0, bv1;
        if (MODE == 2) { bv0 = g_Bsk[col]; bv1 = g_Bsk[col + 1]; }
        else           { bv0 = bA[col]; bv1 = bA[col + 1]; }
#pragma unroll
        for (int i = 0; i < 4; i++)
#pragma unroll
            for (int h = 0; h < 2; h++) {
                int na = n0 + wn * 64 + i * 16 + h * 8 + (lane >> 2);
                float v0 = acc[i][j][h * 2] + bv0;
                float v1 = acc[i][j][h * 2 + 1] + bv1;
                if (MODE == 2 || MODE == 3) {
                    float r0 = fmaxf(v0, 0.f), r1 = fmaxf(v1, 0.f);
                    __half h0, m0, h1, m1;
                    msplit(r0, h0, m0); msplit(r1, h1, m1);
                    __half2 hp; hp.x = h0; hp.y = h1;
                    __half2 mp; mp.x = m0; mp.y = m1;
                    __half* Oh = (MODE == 2) ? g_ShP : g_HhP;
                    __half* Om = (MODE == 2) ? g_SmP : g_HmP;
                    *reinterpret_cast<__half2*>(Oh + (size_t)na * 256 + col) = hp;
                    *reinterpret_cast<__half2*>(Om + (size_t)na * 256 + col) = mp;
                } else {
                    int b = na >> 14, t = na & (T_LEN - 1);
                    dout[((size_t)b * 256 + col) * T_LEN + t]     = v0;
                    dout[((size_t)b * 256 + col + 1) * T_LEN + t] = v1;
                }
            }
    }
}

// ---------------- launch ----------------
extern "C" void kernel_launch(void* const* d_in, const int* in_sizes, int n_in,
                              void* d_out, int out_size) {
    const float* wave  = (const float*)d_in[0];
    const float* W_in  = (const float*)d_in[1];
    const float* b_in  = (const float*)d_in[2];
    const float* Wf    = (const float*)d_in[3];
    const float* bf    = (const float*)d_in[4];
    const float* Wg    = (const float*)d_in[5];
    const float* bg    = (const float*)d_in[6];
    const float* Wres  = (const float*)d_in[7];
    const float* bres  = (const float*)d_in[8];
    const float* Wskip = (const float*)d_in[9];
    const float* bskip = (const float*)d_in[10];
    const float* W1    = (const float*)d_in[11];
    const float* b1    = (const float*)d_in[12];
    const float* W2    = (const float*)d_in[13];
    const float* b2    = (const float*)d_in[14];
    float* out = (float*)d_out;

    const int GS = 4 * 36864;   // 147456
    cudaFuncSetAttribute(fgres_kernel, cudaFuncAttributeMaxDynamicSharedMemorySize, FS_BYTES);
    cudaFuncSetAttribute(mma_kernel<2, 64, 1>, cudaFuncAttributeMaxDynamicSharedMemorySize, GS);
    cudaFuncSetAttribute(mma_kernel<3, 15, 2>, cudaFuncAttributeMaxDynamicSharedMemorySize, GS);
    cudaFuncSetAttribute(mma_kernel<4, 16, 2>, cudaFuncAttributeMaxDynamicSharedMemorySize, GS);

    pack_fg<<<16 * 2 * 15 * 4096 / 256, 256>>>(Wf, Wg);
    pack_rs<<<16 * 8 * 2048 / 256, 256>>>(Wres);
    pack_sk<<<2 * 128 * 2048 / 256, 256>>>(Wskip, bskip);
    pack_h <<<2 * 16 * 2048 / 256, 256>>>(W1, W2);
    init_kernel<<<(size_t)NTOT * 128 / 256, 256>>>(wave, W_in, b_in);

    static const int dil[NBLK] = {1, 2, 4, 8, 16, 32, 64, 128,
                                  1, 2, 4, 8, 16, 32, 64, 128};

    for (int i = 0; i < NBLK; i++)
        fgres_kernel<<<NTOT / 128, 512, FS_BYTES>>>(i, dil[i], bf, bg, bres);

    mma_kernel<2, 64, 1><<<NTOT / 128, 512, GS>>>(nullptr, nullptr);   // skip
    mma_kernel<3, 15, 2><<<NTOT / 128, 512, GS>>>(b1, nullptr);        // head1 (K=240 exact)
    mma_kernel<4, 16, 2><<<NTOT / 128, 512, GS>>>(b2, out);            // head2
}